// round 1
// baseline (speedup 1.0000x reference)
#include <cuda_runtime.h>
#include <cuda_bf16.h>
#include <math.h>
#include <stdint.h>

#define NTOK 8192
#define DDIM 1024
#define HDIM 4096
#define NEXP 8
#define NPAIR (NTOK * 2)

#define BM 128
#define BN 128
#define BK 32
#define APITCH 40    // halves; 80B row pitch -> conflict-free ldmatrix phases
#define BPITCH 136   // halves; 272B row pitch -> conflict-free ldmatrix phases

// ---------------- scratch (device globals: allocation-free rule) ----------------
__device__ float g_h[(size_t)NPAIR * HDIM];   // relu(x@W1)^2, grouped by expert
__device__ float g_ys[(size_t)NPAIR * DDIM];  // per-pair gated expert output
__device__ int   g_tl[NPAIR];                 // pair id (t*2+s) per grouped slot
__device__ float g_gl[NPAIR];                 // gate per grouped slot
__device__ int   g_counts[NEXP];
__device__ int   g_offsets[NEXP + 1];
__device__ int   g_cursor[NEXP];
__device__ int   g_tok_e[NTOK];               // e0 | e1<<8
__device__ float g_tok_g[NTOK * 2];

// ---------------- small kernels ----------------
__global__ void zero_meta_kernel() {
    int i = threadIdx.x;
    if (i < NEXP) { g_counts[i] = 0; g_cursor[i] = 0; }
}

__global__ void route_kernel(const float* __restrict__ x,
                             const float* __restrict__ noisep,
                             const float* __restrict__ Wr,
                             const float* __restrict__ Wn) {
    int warp = threadIdx.x >> 5;
    int lane = threadIdx.x & 31;
    int t = blockIdx.x * 8 + warp;
    if (t >= NTOK) return;

    const float* xr = x + (size_t)t * DDIM;
    float xs[32];
#pragma unroll
    for (int i = 0; i < 32; i++) xs[i] = xr[lane + 32 * i];

    float nz[NEXP];
#pragma unroll
    for (int e = 0; e < NEXP; e++) {
        const float* wr = Wr + e * DDIM;
        const float* wn = Wn + e * DDIM;
        float a = 0.f, b = 0.f;
#pragma unroll
        for (int i = 0; i < 32; i++) {
            float xv = xs[i];
            a = fmaf(xv, wr[lane + 32 * i], a);
            b = fmaf(xv, wn[lane + 32 * i], b);
        }
#pragma unroll
        for (int o = 16; o > 0; o >>= 1) {
            a += __shfl_xor_sync(0xffffffffu, a, o);
            b += __shfl_xor_sync(0xffffffffu, b, o);
        }
        // softplus (stable), matches jax.nn.softplus
        float sp = fmaxf(b, 0.f) + log1pf(expf(-fabsf(b)));
        nz[e] = a + noisep[t * NEXP + e] * sp;
    }

    if (lane == 0) {
        int e0 = 0; float v0 = nz[0];
#pragma unroll
        for (int e = 1; e < NEXP; e++) if (nz[e] > v0) { v0 = nz[e]; e0 = e; }
        int e1 = (e0 == 0) ? 1 : 0; float v1 = nz[e1];
#pragma unroll
        for (int e = 0; e < NEXP; e++)
            if (e != e0 && nz[e] > v1) { v1 = nz[e]; e1 = e; }
        // softmax over the two selected logits (others are -inf => 0)
        float m  = fmaxf(v0, v1);
        float z0 = expf(v0 - m), z1 = expf(v1 - m);
        float inv = 1.f / (z0 + z1);
        g_tok_e[t] = e0 | (e1 << 8);
        g_tok_g[t * 2 + 0] = z0 * inv;
        g_tok_g[t * 2 + 1] = z1 * inv;
        atomicAdd(&g_counts[e0], 1);
        atomicAdd(&g_counts[e1], 1);
    }
}

__global__ void scan_kernel() {
    if (threadIdx.x == 0) {
        int s = 0;
        for (int e = 0; e < NEXP; e++) { g_offsets[e] = s; s += g_counts[e]; }
        g_offsets[NEXP] = s;
    }
}

__global__ void build_kernel() {
    int t = blockIdx.x * blockDim.x + threadIdx.x;
    if (t >= NTOK) return;
    int ee = g_tok_e[t];
    int e0 = ee & 0xff, e1 = ee >> 8;
    int s  = atomicAdd(&g_cursor[e0], 1);
    int i0 = g_offsets[e0] + s;
    g_tl[i0] = t * 2;     g_gl[i0] = g_tok_g[t * 2];
    s = atomicAdd(&g_cursor[e1], 1);
    int i1 = g_offsets[e1] + s;
    g_tl[i1] = t * 2 + 1; g_gl[i1] = g_tok_g[t * 2 + 1];
}

// ---------------- mma helpers ----------------
__device__ __forceinline__ void ldsm4(uint32_t (&r)[4], const __nv_bfloat16* p) {
    uint32_t a = (uint32_t)__cvta_generic_to_shared(p);
    asm volatile("ldmatrix.sync.aligned.m8n8.x4.shared.b16 {%0,%1,%2,%3}, [%4];\n"
                 : "=r"(r[0]), "=r"(r[1]), "=r"(r[2]), "=r"(r[3]) : "r"(a));
}
__device__ __forceinline__ void ldsm4t(uint32_t (&r)[4], const __nv_bfloat16* p) {
    uint32_t a = (uint32_t)__cvta_generic_to_shared(p);
    asm volatile("ldmatrix.sync.aligned.m8n8.x4.trans.shared.b16 {%0,%1,%2,%3}, [%4];\n"
                 : "=r"(r[0]), "=r"(r[1]), "=r"(r[2]), "=r"(r[3]) : "r"(a));
}
__device__ __forceinline__ void mma16816(float (&c)[4], const uint32_t (&a)[4],
                                         const uint32_t (&b)[2]) {
    asm volatile(
        "mma.sync.aligned.m16n8k16.row.col.f32.bf16.bf16.f32 "
        "{%0,%1,%2,%3},{%4,%5,%6,%7},{%8,%9},{%0,%1,%2,%3};\n"
        : "+f"(c[0]), "+f"(c[1]), "+f"(c[2]), "+f"(c[3])
        : "r"(a[0]), "r"(a[1]), "r"(a[2]), "r"(a[3]), "r"(b[0]), "r"(b[1]));
}

__device__ __forceinline__ void split_store4(float4 v, __nv_bfloat16* hi,
                                             __nv_bfloat16* lo) {
    float f[4] = {v.x, v.y, v.z, v.w};
#pragma unroll
    for (int j = 0; j < 4; j++) {
        __nv_bfloat16 h = __float2bfloat16(f[j]);
        hi[j] = h;
        lo[j] = __float2bfloat16(f[j] - __bfloat162float(h));
    }
}

// ---------------- grouped GEMM ----------------
// MODE 0: h[off+m, :] = relu( x[tl] @ W1[e] )^2        (M=cnt, N=4096, K=1024)
// MODE 1: ys[pair, :] = gate * ( h[off+m, :] @ W2[e] ) (M=cnt, N=1024, K=4096)
template <int MODE>
__global__ __launch_bounds__(256, 1)
void moe_gemm(const float* __restrict__ Xin, const float* __restrict__ W) {
    constexpr int K  = (MODE == 0) ? DDIM : HDIM;
    constexpr int NB = (MODE == 0) ? HDIM : DDIM;  // B row length == C ld

    const int e     = blockIdx.z;
    const int mTile = (MODE == 0) ? blockIdx.x : blockIdx.y;
    const int nTile = (MODE == 0) ? blockIdx.y : blockIdx.x;
    const int cnt   = g_counts[e];
    if (mTile * BM >= cnt) return;
    const int off   = g_offsets[e];
    const int nbase = nTile * BN;

    const float* A0 = (MODE == 0) ? Xin : g_h;
    float*       C  = (MODE == 0) ? g_h : g_ys;

    __shared__ __nv_bfloat16 sA[2][BM][APITCH];  // [hi/lo]
    __shared__ __nv_bfloat16 sB[2][BK][BPITCH];

    const int tid = threadIdx.x;

    // per-thread global-load pointers (4 float4 for A, 4 for B per stage)
    const float* aP[4];
    {
        int c4 = (tid & 7) * 4;
#pragma unroll
        for (int i = 0; i < 4; i++) {
            int r  = (tid >> 3) + i * 32;
            int gm = mTile * BM + r;
            int rm = min(gm, cnt - 1);
            const float* rowp;
            if (MODE == 0) {
                int pr = g_tl[off + rm];
                rowp = A0 + (size_t)(pr >> 1) * DDIM;
            } else {
                rowp = A0 + (size_t)(off + rm) * HDIM;
            }
            aP[i] = rowp + c4;
        }
    }
    const float* bP[4];
    {
        int c4 = (tid & 31) * 4;
        const float* wb = W + (size_t)e * K * NB + nbase + c4;
#pragma unroll
        for (int i = 0; i < 4; i++) {
            int r = (tid >> 5) + i * 8;
            bP[i] = wb + (size_t)r * NB;
        }
    }

    float4 aS[4], bS[4];
#pragma unroll
    for (int i = 0; i < 4; i++) aS[i] = *(const float4*)(aP[i]);
#pragma unroll
    for (int i = 0; i < 4; i++) bS[i] = *(const float4*)(bP[i]);

    {   // prologue smem fill
#pragma unroll
        for (int i = 0; i < 4; i++) {
            int r = (tid >> 3) + i * 32, c = (tid & 7) * 4;
            split_store4(aS[i], &sA[0][r][c], &sA[1][r][c]);
        }
#pragma unroll
        for (int i = 0; i < 4; i++) {
            int r = (tid >> 5) + i * 8, c = (tid & 31) * 4;
            split_store4(bS[i], &sB[0][r][c], &sB[1][r][c]);
        }
    }
    __syncthreads();

    const int warp = tid >> 5, lane = tid & 31;
    const int wm = (warp >> 1) * 32;   // 4x2 warp grid -> 32x64 warp tile
    const int wn = (warp & 1) * 64;

    float acc[2][8][4];
#pragma unroll
    for (int a = 0; a < 2; a++)
#pragma unroll
        for (int b = 0; b < 8; b++)
#pragma unroll
            for (int c = 0; c < 4; c++) acc[a][b][c] = 0.f;

    const int aRow  = lane & 15;
    const int aCol  = (lane >> 4) << 3;
    const int bRowL = ((lane >> 3) & 1) * 8 + (lane & 7);
    const int bColL = (lane >> 4) * 8;

    for (int k0 = 0; k0 < K; k0 += BK) {
        bool next = (k0 + BK) < K;
        if (next) {
#pragma unroll
            for (int i = 0; i < 4; i++)
                aS[i] = *(const float4*)(aP[i] + k0 + BK);
#pragma unroll
            for (int i = 0; i < 4; i++)
                bS[i] = *(const float4*)(bP[i] + (size_t)(k0 + BK) * NB);
        }

#pragma unroll
        for (int ks = 0; ks < 2; ks++) {
            uint32_t af[2][2][4];  // [hi/lo][m-subtile]
#pragma unroll
            for (int p = 0; p < 2; p++)
#pragma unroll
                for (int ms = 0; ms < 2; ms++)
                    ldsm4(af[p][ms], &sA[p][wm + ms * 16 + aRow][ks * 16 + aCol]);

            uint32_t bf[2][8][2];  // [hi/lo][n-subtile]
#pragma unroll
            for (int p = 0; p < 2; p++)
#pragma unroll
                for (int g = 0; g < 4; g++) {
                    uint32_t q[4];
                    ldsm4t(q, &sB[p][ks * 16 + bRowL][wn + g * 16 + bColL]);
                    bf[p][g * 2 + 0][0] = q[0]; bf[p][g * 2 + 0][1] = q[1];
                    bf[p][g * 2 + 1][0] = q[2]; bf[p][g * 2 + 1][1] = q[3];
                }

#pragma unroll
            for (int ms = 0; ms < 2; ms++)
#pragma unroll
                for (int ns = 0; ns < 8; ns++) {
                    mma16816(acc[ms][ns], af[0][ms], bf[0][ns]);  // hi*hi
                    mma16816(acc[ms][ns], af[0][ms], bf[1][ns]);  // hi*lo
                    mma16816(acc[ms][ns], af[1][ms], bf[0][ns]);  // lo*hi
                }
        }
        __syncthreads();
        if (next) {
#pragma unroll
            for (int i = 0; i < 4; i++) {
                int r = (tid >> 3) + i * 32, c = (tid & 7) * 4;
                split_store4(aS[i], &sA[0][r][c], &sA[1][r][c]);
            }
#pragma unroll
            for (int i = 0; i < 4; i++) {
                int r = (tid >> 5) + i * 8, c = (tid & 31) * 4;
                split_store4(bS[i], &sB[0][r][c], &sB[1][r][c]);
            }
        }
        __syncthreads();
    }

    // epilogue
#pragma unroll
    for (int ms = 0; ms < 2; ms++) {
        int r0 = wm + ms * 16 + (lane >> 2);
#pragma unroll
        for (int half = 0; half < 2; half++) {
            int r  = r0 + half * 8;
            int gm = mTile * BM + r;
            if (gm < cnt) {
                if (MODE == 0) {
                    float* crow = C + (size_t)(off + gm) * HDIM + nbase;
#pragma unroll
                    for (int ns = 0; ns < 8; ns++) {
                        int cc  = wn + ns * 8 + (lane & 3) * 2;
                        float v0 = fmaxf(acc[ms][ns][half * 2 + 0], 0.f);
                        float v1 = fmaxf(acc[ms][ns][half * 2 + 1], 0.f);
                        *(float2*)(crow + cc) = make_float2(v0 * v0, v1 * v1);
                    }
                } else {
                    int   idx = off + gm;
                    int   pr  = g_tl[idx];
                    float gt  = g_gl[idx];
                    float* crow = C + (size_t)pr * DDIM + nbase;
#pragma unroll
                    for (int ns = 0; ns < 8; ns++) {
                        int cc = wn + ns * 8 + (lane & 3) * 2;
                        *(float2*)(crow + cc) =
                            make_float2(acc[ms][ns][half * 2 + 0] * gt,
                                        acc[ms][ns][half * 2 + 1] * gt);
                    }
                }
            }
        }
    }
}

__global__ void combine_kernel(float* __restrict__ out) {
    size_t i = (size_t)blockIdx.x * blockDim.x + threadIdx.x;  // float4 idx
    const float4* ys = (const float4*)g_ys;
    size_t t = i >> 8;         // DDIM/4 = 256 float4 per token
    size_t d = i & 255;
    float4 a = ys[(t * 2 + 0) * 256 + d];
    float4 b = ys[(t * 2 + 1) * 256 + d];
    ((float4*)out)[i] = make_float4(a.x + b.x, a.y + b.y, a.z + b.z, a.w + b.w);
}

// ---------------- launcher ----------------
extern "C" void kernel_launch(void* const* d_in, const int* in_sizes, int n_in,
                              void* d_out, int out_size) {
    const float* x  = (const float*)d_in[0];
    const float* nz = (const float*)d_in[1];
    const float* Wr = (const float*)d_in[2];
    const float* Wn = (const float*)d_in[3];
    const float* W1 = (const float*)d_in[4];
    const float* W2 = (const float*)d_in[5];
    float* out = (float*)d_out;

    zero_meta_kernel<<<1, 32>>>();
    route_kernel<<<NTOK / 8, 256>>>(x, nz, Wr, Wn);
    scan_kernel<<<1, 32>>>();
    build_kernel<<<NTOK / 256, 256>>>();

    // GEMM1: m fastest -> consecutive CTAs share the same W1 N-slice via L2
    moe_gemm<0><<<dim3(NTOK / BM, HDIM / BN, NEXP), 256>>>(x, W1);
    // GEMM2: n fastest -> consecutive CTAs share the same h M-slice via L2
    moe_gemm<1><<<dim3(DDIM / BN, NTOK / BM, NEXP), 256>>>(x, W2);

    combine_kernel<<<(NTOK * DDIM / 4) / 256, 256>>>(out);
}

// round 3
// speedup vs baseline: 1.1155x; 1.1155x over previous
#include <cuda_runtime.h>
#include <cuda_bf16.h>
#include <math.h>
#include <stdint.h>

#define NTOK 8192
#define DDIM 1024
#define HDIM 4096
#define NEXP 8
#define NPAIR (NTOK * 2)

// ---------------- scratch (device globals: allocation-free rule) ----------------
__device__ __nv_bfloat16 gXh[(size_t)NPAIR * DDIM];
__device__ __nv_bfloat16 gXl[(size_t)NPAIR * DDIM];
__device__ __nv_bfloat16 gHh[(size_t)NPAIR * HDIM];
__device__ __nv_bfloat16 gHl[(size_t)NPAIR * HDIM];
__device__ __nv_bfloat16 gW1h[(size_t)NEXP * DDIM * HDIM];  // [e][k=D][n=H]
__device__ __nv_bfloat16 gW1l[(size_t)NEXP * DDIM * HDIM];
__device__ __nv_bfloat16 gW2h[(size_t)NEXP * HDIM * DDIM];  // [e][k=H][n=D]
__device__ __nv_bfloat16 gW2l[(size_t)NEXP * HDIM * DDIM];
__device__ float g_ys[(size_t)NPAIR * DDIM];
__device__ int   g_tl[NPAIR];
__device__ float g_gl[NPAIR];
__device__ int   g_counts[NEXP];
__device__ int   g_offsets[NEXP + 1];
__device__ int   g_cursor[NEXP];
__device__ int   g_tok_e[NTOK];
__device__ float g_tok_g[NTOK * 2];

// ---------------- small kernels ----------------
__global__ void zero_meta_kernel() {
    int i = threadIdx.x;
    if (i < NEXP) { g_counts[i] = 0; g_cursor[i] = 0; }
}

__global__ void route_kernel(const float* __restrict__ x,
                             const float* __restrict__ noisep,
                             const float* __restrict__ Wr,
                             const float* __restrict__ Wn) {
    int warp = threadIdx.x >> 5;
    int lane = threadIdx.x & 31;
    int t = blockIdx.x * 8 + warp;
    if (t >= NTOK) return;

    const float* xr = x + (size_t)t * DDIM;
    float xs[32];
#pragma unroll
    for (int i = 0; i < 32; i++) xs[i] = xr[lane + 32 * i];

    float nz[NEXP];
#pragma unroll
    for (int e = 0; e < NEXP; e++) {
        const float* wr = Wr + e * DDIM;
        const float* wn = Wn + e * DDIM;
        float a = 0.f, b = 0.f;
#pragma unroll
        for (int i = 0; i < 32; i++) {
            float xv = xs[i];
            a = fmaf(xv, wr[lane + 32 * i], a);
            b = fmaf(xv, wn[lane + 32 * i], b);
        }
#pragma unroll
        for (int o = 16; o > 0; o >>= 1) {
            a += __shfl_xor_sync(0xffffffffu, a, o);
            b += __shfl_xor_sync(0xffffffffu, b, o);
        }
        float sp = fmaxf(b, 0.f) + log1pf(expf(-fabsf(b)));
        nz[e] = a + noisep[t * NEXP + e] * sp;
    }

    if (lane == 0) {
        int e0 = 0; float v0 = nz[0];
#pragma unroll
        for (int e = 1; e < NEXP; e++) if (nz[e] > v0) { v0 = nz[e]; e0 = e; }
        int e1 = (e0 == 0) ? 1 : 0; float v1 = nz[e1];
#pragma unroll
        for (int e = 0; e < NEXP; e++)
            if (e != e0 && nz[e] > v1) { v1 = nz[e]; e1 = e; }
        float m  = fmaxf(v0, v1);
        float z0 = expf(v0 - m), z1 = expf(v1 - m);
        float inv = 1.f / (z0 + z1);
        g_tok_e[t] = e0 | (e1 << 8);
        g_tok_g[t * 2 + 0] = z0 * inv;
        g_tok_g[t * 2 + 1] = z1 * inv;
        atomicAdd(&g_counts[e0], 1);
        atomicAdd(&g_counts[e1], 1);
    }
}

__global__ void scan_kernel() {
    if (threadIdx.x == 0) {
        int s = 0;
        for (int e = 0; e < NEXP; e++) { g_offsets[e] = s; s += g_counts[e]; }
        g_offsets[NEXP] = s;
    }
}

__global__ void build_kernel() {
    int t = blockIdx.x * blockDim.x + threadIdx.x;
    if (t >= NTOK) return;
    int ee = g_tok_e[t];
    int e0 = ee & 0xff, e1 = ee >> 8;
    int s  = atomicAdd(&g_cursor[e0], 1);
    int i0 = g_offsets[e0] + s;
    g_tl[i0] = t * 2;     g_gl[i0] = g_tok_g[t * 2];
    s = atomicAdd(&g_cursor[e1], 1);
    int i1 = g_offsets[e1] + s;
    g_tl[i1] = t * 2 + 1; g_gl[i1] = g_tok_g[t * 2 + 1];
}

// ---------------- split helpers ----------------
__device__ __forceinline__ uint32_t pack_hi2(float a, float b) {
    __nv_bfloat16 h0 = __float2bfloat16(a), h1 = __float2bfloat16(b);
    return (uint32_t)__bfloat16_as_ushort(h0) |
           ((uint32_t)__bfloat16_as_ushort(h1) << 16);
}
__device__ __forceinline__ uint32_t pack_lo2(float a, float b) {
    __nv_bfloat16 h0 = __float2bfloat16(a), h1 = __float2bfloat16(b);
    float l0 = a - __bfloat162float(h0);
    float l1 = b - __bfloat162float(h1);
    __nv_bfloat16 g0 = __float2bfloat16(l0), g1 = __float2bfloat16(l1);
    return (uint32_t)__bfloat16_as_ushort(g0) |
           ((uint32_t)__bfloat16_as_ushort(g1) << 16);
}

__global__ void gatherx_kernel(const float* __restrict__ x) {
    int idx = blockIdx.x;                 // grouped slot
    int t = g_tl[idx] >> 1;               // token
    float4 v = ((const float4*)(x + (size_t)t * DDIM))[threadIdx.x];
    size_t o = (size_t)idx * DDIM + threadIdx.x * 4;
    *(uint2*)(gXh + o) = make_uint2(pack_hi2(v.x, v.y), pack_hi2(v.z, v.w));
    *(uint2*)(gXl + o) = make_uint2(pack_lo2(v.x, v.y), pack_lo2(v.z, v.w));
}

// elementwise split of weights (layouts already K-major for both GEMMs)
template <int MODE>  // 0: W1 (E*D*H elems) -> gW1h/l ; 1: W2 -> gW2h/l
__global__ void splitw_kernel(const float* __restrict__ W) {
    __nv_bfloat16* oh = (MODE == 0) ? gW1h : gW2h;
    __nv_bfloat16* ol = (MODE == 0) ? gW1l : gW2l;
    size_t i = (size_t)blockIdx.x * blockDim.x + threadIdx.x;  // float4 idx
    float4 v = ((const float4*)W)[i];
    *(uint2*)(oh + i * 4) = make_uint2(pack_hi2(v.x, v.y), pack_hi2(v.z, v.w));
    *(uint2*)(ol + i * 4) = make_uint2(pack_lo2(v.x, v.y), pack_lo2(v.z, v.w));
}

// ---------------- mma helpers ----------------
__device__ __forceinline__ void ldsm4(uint32_t (&r)[4], uint32_t a) {
    asm volatile("ldmatrix.sync.aligned.m8n8.x4.shared.b16 {%0,%1,%2,%3}, [%4];\n"
                 : "=r"(r[0]), "=r"(r[1]), "=r"(r[2]), "=r"(r[3]) : "r"(a));
}
__device__ __forceinline__ void ldsm4t(uint32_t (&r)[4], uint32_t a) {
    asm volatile("ldmatrix.sync.aligned.m8n8.x4.trans.shared.b16 {%0,%1,%2,%3}, [%4];\n"
                 : "=r"(r[0]), "=r"(r[1]), "=r"(r[2]), "=r"(r[3]) : "r"(a));
}
__device__ __forceinline__ void mma16816(float (&c)[4], const uint32_t (&a)[4],
                                         const uint32_t (&b)[2]) {
    asm volatile(
        "mma.sync.aligned.m16n8k16.row.col.f32.bf16.bf16.f32 "
        "{%0,%1,%2,%3},{%4,%5,%6,%7},{%8,%9},{%0,%1,%2,%3};\n"
        : "+f"(c[0]), "+f"(c[1]), "+f"(c[2]), "+f"(c[3])
        : "r"(a[0]), "r"(a[1]), "r"(a[2]), "r"(a[3]), "r"(b[0]), "r"(b[1]));
}
__device__ __forceinline__ void cpa16(uint32_t d, const void* s) {
    asm volatile("cp.async.cg.shared.global [%0], [%1], 16;" :: "r"(d), "l"(s)
                 : "memory");
}
__device__ __forceinline__ void cpa_commit() {
    asm volatile("cp.async.commit_group;" ::: "memory");
}
__device__ __forceinline__ void cpa_wait1() {
    asm volatile("cp.async.wait_group 1;" ::: "memory");
}

// smem stage layout (bytes): Ah[128][40h]=10240 | Al=10240 | Bh[32][136h]=8704 | Bl=8704
#define OFF_AL 10240
#define OFF_BH 20480
#define OFF_BL 29184
#define STG    37888
#define NSTAGE 3
#define DSMEM  (NSTAGE * STG)

// ---------------- grouped split-bf16 mma.sync GEMM ----------------
// MODE 0: h[idx,:]  = relu(gX[idx,:] @ W1[e])^2  -> gHh/gHl   (K=1024, N=4096)
// MODE 1: ys[pr,:]  = gate * (gH[idx,:] @ W2[e]) -> g_ys      (K=4096, N=1024)
template <int MODE>
__global__ __launch_bounds__(256, 1)
void moe_mma() {
    constexpr int K   = (MODE == 0) ? DDIM : HDIM;
    constexpr int NGL = (MODE == 0) ? HDIM : DDIM;
    constexpr int NC  = K / 32;

    const int e   = blockIdx.z;
    const int cnt = g_counts[e];
    const int mT  = (MODE == 0) ? blockIdx.x : blockIdx.y;
    if (mT * 128 >= cnt) return;
    const int nT  = (MODE == 0) ? blockIdx.y : blockIdx.x;
    const int off = g_offsets[e];
    const int nb  = nT * 128;

    extern __shared__ char dsm[];
    const uint32_t ab = (uint32_t)__cvta_generic_to_shared(dsm);

    const int tid = threadIdx.x;
    const int warp = tid >> 5, lane = tid & 31;

    const __nv_bfloat16* Ah = (MODE == 0) ? gXh : gHh;
    const __nv_bfloat16* Al = (MODE == 0) ? gXl : gHl;
    const __nv_bfloat16* Bh = ((MODE == 0) ? gW1h : gW2h) + (size_t)e * DDIM * HDIM;
    const __nv_bfloat16* Bl = ((MODE == 0) ? gW1l : gW2l) + (size_t)e * DDIM * HDIM;

    // ---- per-thread cp.async slots: A 2 rows x 16B, B 2 rows x 16B (x hi/lo) ----
    const int aC = tid & 3;           // 16B col within 64B row
    const int aR = tid >> 2;          // 0..63
    size_t   aSrc[2]; uint32_t aDst[2];
#pragma unroll
    for (int i = 0; i < 2; i++) {
        int r  = aR + i * 64;
        int gm = off + min(mT * 128 + r, cnt - 1);
        aSrc[i] = (size_t)gm * K + aC * 8;
        aDst[i] = (uint32_t)(r * 80 + aC * 16);
    }
    const int bC = tid & 15;          // 16B col within 256B row
    const int bR = tid >> 4;          // 0..15
    size_t   bSrc[2]; uint32_t bDst[2];
#pragma unroll
    for (int i = 0; i < 2; i++) {
        int r = bR + i * 16;
        bSrc[i] = (size_t)r * NGL + nb + bC * 8;
        bDst[i] = (uint32_t)(r * 272 + bC * 16);
    }

    auto ldc = [&](int c) {
        uint32_t sb = ab + (uint32_t)(c % NSTAGE) * STG;
        int k0 = c * 32;
#pragma unroll
        for (int i = 0; i < 2; i++) {
            cpa16(sb + aDst[i],          Ah + aSrc[i] + k0);
            cpa16(sb + OFF_AL + aDst[i], Al + aSrc[i] + k0);
        }
        size_t bk = (size_t)k0 * NGL;
#pragma unroll
        for (int i = 0; i < 2; i++) {
            cpa16(sb + OFF_BH + bDst[i], Bh + bSrc[i] + bk);
            cpa16(sb + OFF_BL + bDst[i], Bl + bSrc[i] + bk);
        }
        cpa_commit();
    };

    ldc(0);
    ldc(1);

    const int wm = (warp >> 1) * 32;   // 4x2 warp grid -> 32x64 warp tile
    const int wn = (warp & 1) * 64;

    float acc[2][8][4];
#pragma unroll
    for (int a = 0; a < 2; a++)
#pragma unroll
        for (int b = 0; b < 8; b++)
#pragma unroll
            for (int c = 0; c < 4; c++) acc[a][b][c] = 0.f;

    const int aRow  = lane & 15;
    const int aCol  = (lane >> 4) << 3;
    const int bRowL = ((lane >> 3) & 1) * 8 + (lane & 7);
    const int bColL = (lane >> 4) * 8;

    for (int c = 0; c < NC; c++) {
        cpa_wait1();
        __syncthreads();
        if (c + 2 < NC) ldc(c + 2); else cpa_commit();

        uint32_t sb = ab + (uint32_t)(c % NSTAGE) * STG;
#pragma unroll
        for (int ks = 0; ks < 2; ks++) {
            uint32_t af[2][2][4];  // [hi/lo][m-subtile]
#pragma unroll
            for (int p = 0; p < 2; p++)
#pragma unroll
                for (int ms = 0; ms < 2; ms++)
                    ldsm4(af[p][ms],
                          sb + p * OFF_AL +
                          (uint32_t)((wm + ms * 16 + aRow) * 80 +
                                     (ks * 16 + aCol) * 2));

            uint32_t bf[2][8][2];  // [hi/lo][n-subtile]
#pragma unroll
            for (int p = 0; p < 2; p++)
#pragma unroll
                for (int g = 0; g < 4; g++) {
                    uint32_t q[4];
                    ldsm4t(q, sb + OFF_BH + p * (OFF_BL - OFF_BH) +
                              (uint32_t)((ks * 16 + bRowL) * 272 +
                                         (wn + g * 16 + bColL) * 2));
                    bf[p][g * 2 + 0][0] = q[0]; bf[p][g * 2 + 0][1] = q[1];
                    bf[p][g * 2 + 1][0] = q[2]; bf[p][g * 2 + 1][1] = q[3];
                }

#pragma unroll
            for (int ms = 0; ms < 2; ms++)
#pragma unroll
                for (int ns = 0; ns < 8; ns++) {
                    mma16816(acc[ms][ns], af[0][ms], bf[0][ns]);  // hi*hi
                    mma16816(acc[ms][ns], af[0][ms], bf[1][ns]);  // hi*lo
                    mma16816(acc[ms][ns], af[1][ms], bf[0][ns]);  // lo*hi
                }
        }
        __syncthreads();
    }

    // ---------------- epilogue ----------------
#pragma unroll
    for (int ms = 0; ms < 2; ms++) {
        int r0 = wm + ms * 16 + (lane >> 2);
#pragma unroll
        for (int half = 0; half < 2; half++) {
            int r  = r0 + half * 8;
            int gm = mT * 128 + r;
            if (gm < cnt) {
                int idx = off + gm;
                if (MODE == 0) {
                    __nv_bfloat16* oh = gHh + (size_t)idx * HDIM + nb;
                    __nv_bfloat16* ol = gHl + (size_t)idx * HDIM + nb;
#pragma unroll
                    for (int ns = 0; ns < 8; ns++) {
                        int cc  = wn + ns * 8 + (lane & 3) * 2;
                        float v0 = fmaxf(acc[ms][ns][half * 2 + 0], 0.f);
                        float v1 = fmaxf(acc[ms][ns][half * 2 + 1], 0.f);
                        v0 *= v0; v1 *= v1;
                        *(uint32_t*)(oh + cc) = pack_hi2(v0, v1);
                        *(uint32_t*)(ol + cc) = pack_lo2(v0, v1);
                    }
                } else {
                    int   pr = g_tl[idx];
                    float gt = g_gl[idx];
                    float* yo = g_ys + (size_t)pr * DDIM + nb;
#pragma unroll
                    for (int ns = 0; ns < 8; ns++) {
                        int cc = wn + ns * 8 + (lane & 3) * 2;
                        *(float2*)(yo + cc) =
                            make_float2(acc[ms][ns][half * 2 + 0] * gt,
                                        acc[ms][ns][half * 2 + 1] * gt);
                    }
                }
            }
        }
    }
}

__global__ void combine_kernel(float* __restrict__ out) {
    size_t i = (size_t)blockIdx.x * blockDim.x + threadIdx.x;  // float4 idx
    const float4* ys = (const float4*)g_ys;
    size_t t = i >> 8;
    size_t d = i & 255;
    float4 a = ys[(t * 2 + 0) * 256 + d];
    float4 b = ys[(t * 2 + 1) * 256 + d];
    ((float4*)out)[i] = make_float4(a.x + b.x, a.y + b.y, a.z + b.z, a.w + b.w);
}

// ---------------- launcher ----------------
extern "C" void kernel_launch(void* const* d_in, const int* in_sizes, int n_in,
                              void* d_out, int out_size) {
    const float* x  = (const float*)d_in[0];
    const float* nz = (const float*)d_in[1];
    const float* Wr = (const float*)d_in[2];
    const float* Wn = (const float*)d_in[3];
    const float* W1 = (const float*)d_in[4];
    const float* W2 = (const float*)d_in[5];
    float* out = (float*)d_out;

    cudaFuncSetAttribute(moe_mma<0>, cudaFuncAttributeMaxDynamicSharedMemorySize, DSMEM);
    cudaFuncSetAttribute(moe_mma<1>, cudaFuncAttributeMaxDynamicSharedMemorySize, DSMEM);

    zero_meta_kernel<<<1, 32>>>();
    route_kernel<<<NTOK / 8, 256>>>(x, nz, Wr, Wn);
    scan_kernel<<<1, 32>>>();
    build_kernel<<<NTOK / 256, 256>>>();

    gatherx_kernel<<<NPAIR, 256>>>(x);
    splitw_kernel<0><<<(NEXP * DDIM * HDIM / 4) / 256, 256>>>(W1);
    splitw_kernel<1><<<(NEXP * DDIM * HDIM / 4) / 256, 256>>>(W2);

    // GEMM1: m fastest -> consecutive CTAs share W1 N-slice via L2
    moe_mma<0><<<dim3(NTOK / 2 / 64, HDIM / 128, NEXP), 256, DSMEM>>>();
    // GEMM2: n fastest -> consecutive CTAs share h M-slice via L2
    moe_mma<1><<<dim3(DDIM / 128, NTOK / 2 / 64, NEXP), 256, DSMEM>>>();

    combine_kernel<<<(NTOK * DDIM / 4) / 256, 256>>>(out);
}

// round 4
// speedup vs baseline: 1.4411x; 1.2919x over previous
#include <cuda_runtime.h>
#include <cuda_fp16.h>
#include <math.h>
#include <stdint.h>

#define NTOK 8192
#define DDIM 1024
#define HDIM 4096
#define NEXP 8
#define NPAIR (NTOK * 2)

// ---------------- scratch (device globals: allocation-free rule) ----------------
__device__ __half gXh[(size_t)NTOK * DDIM];   // fp16 hi of x (token order)
__device__ __half gXl[(size_t)NTOK * DDIM];   // fp16 residual of x
__device__ __half gH[(size_t)NPAIR * HDIM];   // h = relu(u)^2, fp16, grouped
__device__ __half gW1h[(size_t)NEXP * DDIM * HDIM];
__device__ __half gW1l[(size_t)NEXP * DDIM * HDIM];
__device__ __half gW2h[(size_t)NEXP * HDIM * DDIM];
__device__ __half gW2l[(size_t)NEXP * HDIM * DDIM];
__device__ float g_ys[(size_t)NPAIR * DDIM];
__device__ int   g_tl[NPAIR];
__device__ float g_gl[NPAIR];
__device__ int   g_counts[NEXP];
__device__ int   g_offsets[NEXP + 1];
__device__ int   g_cursor[NEXP];
__device__ int   g_tok_e[NTOK];
__device__ float g_tok_g[NTOK * 2];

// ---------------- helpers ----------------
__device__ __forceinline__ uint32_t hpack2(float a, float b) {
    __half2 h = __floats2half2_rn(a, b);
    return *(uint32_t*)&h;
}
__device__ __forceinline__ uint32_t lpack2(float a, float b) {
    float ra = a - __half2float(__float2half_rn(a));
    float rb = b - __half2float(__float2half_rn(b));
    __half2 h = __floats2half2_rn(ra, rb);
    return *(uint32_t*)&h;
}

// ---------------- launch 1: zero meta ----------------
__global__ void zero_meta_kernel() {
    int i = threadIdx.x;
    if (i < NEXP) { g_counts[i] = 0; g_cursor[i] = 0; }
}

// ---------------- launch 2: fused prep (splitW1 | splitW2 | splitX | route) ----
#define PB_W1 32768
#define PB_W2 65536
#define PB_X  73728
#define PB_RT 74752

__global__ __launch_bounds__(256)
void prep_kernel(const float* __restrict__ x, const float* __restrict__ noisep,
                 const float* __restrict__ Wr, const float* __restrict__ Wn,
                 const float* __restrict__ W1, const float* __restrict__ W2) {
    int b = blockIdx.x, tid = threadIdx.x;
    if (b < PB_W2) {
        const float* W = (b < PB_W1) ? W1 : W2;
        __half* oh = (b < PB_W1) ? gW1h : gW2h;
        __half* ol = (b < PB_W1) ? gW1l : gW2l;
        size_t i = ((size_t)(b < PB_W1 ? b : b - PB_W1) * 256 + tid);
        float4 v = ((const float4*)W)[i];
        *(uint2*)(oh + i * 4) = make_uint2(hpack2(v.x, v.y), hpack2(v.z, v.w));
        *(uint2*)(ol + i * 4) = make_uint2(lpack2(v.x, v.y), lpack2(v.z, v.w));
    } else if (b < PB_X) {
        int t = b - PB_W2;
        float4 v = ((const float4*)(x + (size_t)t * DDIM))[tid];
        size_t o = (size_t)t * DDIM + tid * 4;
        *(uint2*)(gXh + o) = make_uint2(hpack2(v.x, v.y), hpack2(v.z, v.w));
        *(uint2*)(gXl + o) = make_uint2(lpack2(v.x, v.y), lpack2(v.z, v.w));
    } else {
        // router: one warp per token
        int warp = tid >> 5, lane = tid & 31;
        int t = (b - PB_X) * 8 + warp;
        const float* xr = x + (size_t)t * DDIM;
        float xs[32];
#pragma unroll
        for (int i = 0; i < 32; i++) xs[i] = xr[lane + 32 * i];
        float nz[NEXP];
#pragma unroll
        for (int e = 0; e < NEXP; e++) {
            const float* wr = Wr + e * DDIM;
            const float* wn = Wn + e * DDIM;
            float a = 0.f, bb = 0.f;
#pragma unroll
            for (int i = 0; i < 32; i++) {
                float xv = xs[i];
                a  = fmaf(xv, wr[lane + 32 * i], a);
                bb = fmaf(xv, wn[lane + 32 * i], bb);
            }
#pragma unroll
            for (int o = 16; o > 0; o >>= 1) {
                a  += __shfl_xor_sync(0xffffffffu, a, o);
                bb += __shfl_xor_sync(0xffffffffu, bb, o);
            }
            float sp = fmaxf(bb, 0.f) + log1pf(expf(-fabsf(bb)));
            nz[e] = a + noisep[t * NEXP + e] * sp;
        }
        if (lane == 0) {
            int e0 = 0; float v0 = nz[0];
#pragma unroll
            for (int e = 1; e < NEXP; e++) if (nz[e] > v0) { v0 = nz[e]; e0 = e; }
            int e1 = (e0 == 0) ? 1 : 0; float v1 = nz[e1];
#pragma unroll
            for (int e = 0; e < NEXP; e++)
                if (e != e0 && nz[e] > v1) { v1 = nz[e]; e1 = e; }
            float m  = fmaxf(v0, v1);
            float z0 = expf(v0 - m), z1 = expf(v1 - m);
            float inv = 1.f / (z0 + z1);
            g_tok_e[t] = e0 | (e1 << 8);
            g_tok_g[t * 2 + 0] = z0 * inv;
            g_tok_g[t * 2 + 1] = z1 * inv;
            atomicAdd(&g_counts[e0], 1);
            atomicAdd(&g_counts[e1], 1);
        }
    }
}

// ---------------- launch 3: scan + build (single CTA) ----------------
__global__ void scanbuild_kernel() {
    int tid = threadIdx.x;
    if (tid == 0) {
        int s = 0;
        for (int e = 0; e < NEXP; e++) { g_offsets[e] = s; s += g_counts[e]; }
        g_offsets[NEXP] = s;
    }
    __syncthreads();
    for (int t = tid; t < NTOK; t += 1024) {
        int ee = g_tok_e[t];
        int e0 = ee & 0xff, e1 = ee >> 8;
        int s  = atomicAdd(&g_cursor[e0], 1);
        int i0 = g_offsets[e0] + s;
        g_tl[i0] = t * 2;     g_gl[i0] = g_tok_g[t * 2];
        s = atomicAdd(&g_cursor[e1], 1);
        int i1 = g_offsets[e1] + s;
        g_tl[i1] = t * 2 + 1; g_gl[i1] = g_tok_g[t * 2 + 1];
    }
}

// ---------------- mma helpers ----------------
__device__ __forceinline__ void ldsm4(uint32_t (&r)[4], uint32_t a) {
    asm volatile("ldmatrix.sync.aligned.m8n8.x4.shared.b16 {%0,%1,%2,%3}, [%4];\n"
                 : "=r"(r[0]), "=r"(r[1]), "=r"(r[2]), "=r"(r[3]) : "r"(a));
}
__device__ __forceinline__ void ldsm4t(uint32_t (&r)[4], uint32_t a) {
    asm volatile("ldmatrix.sync.aligned.m8n8.x4.trans.shared.b16 {%0,%1,%2,%3}, [%4];\n"
                 : "=r"(r[0]), "=r"(r[1]), "=r"(r[2]), "=r"(r[3]) : "r"(a));
}
__device__ __forceinline__ void mma16816(float (&c)[4], const uint32_t (&a)[4],
                                         const uint32_t (&b)[2]) {
    asm volatile(
        "mma.sync.aligned.m16n8k16.row.col.f32.f16.f16.f32 "
        "{%0,%1,%2,%3},{%4,%5,%6,%7},{%8,%9},{%0,%1,%2,%3};\n"
        : "+f"(c[0]), "+f"(c[1]), "+f"(c[2]), "+f"(c[3])
        : "r"(a[0]), "r"(a[1]), "r"(a[2]), "r"(a[3]), "r"(b[0]), "r"(b[1]));
}
__device__ __forceinline__ void cpa16(uint32_t d, const void* s) {
    asm volatile("cp.async.cg.shared.global [%0], [%1], 16;" :: "r"(d), "l"(s)
                 : "memory");
}
__device__ __forceinline__ void cpa_commit() {
    asm volatile("cp.async.commit_group;" ::: "memory");
}
__device__ __forceinline__ void cpa_wait1() {
    asm volatile("cp.async.wait_group 1;" ::: "memory");
}

// smem geometry: BK=64. A rows 144B pitch (72 halves), B rows 272B pitch (136 halves).
// MODE0 stage: Ah 18432 | Al 18432 | Bh 17408 | Bl 17408 = 71680
// MODE1 stage: A  18432 |            Bh 17408 | Bl 17408 = 53248
#define A_BYTES 18432
#define B_BYTES 17408
#define NSTAGE 3

// ---------------- grouped split-fp16 mma.sync GEMM ----------------
// MODE 0 (launch 4): h = relu(x @ W1[e])^2 -> gH (fp16)   K=1024 N=4096, 3 terms
// MODE 1 (launch 5): ys = gate * (h @ W2[e]) -> g_ys      K=4096 N=1024, 2 terms
template <int MODE>
__global__ __launch_bounds__(256, 1)
void moe_mma() {
    constexpr int K      = (MODE == 0) ? DDIM : HDIM;
    constexpr int NGL    = (MODE == 0) ? HDIM : DDIM;
    constexpr int NC     = K / 64;
    constexpr int OFF_AL = A_BYTES;                       // mode0 only
    constexpr int OFF_BH = (MODE == 0) ? 2 * A_BYTES : A_BYTES;
    constexpr int OFF_BL = OFF_BH + B_BYTES;
    constexpr int STG    = OFF_BL + B_BYTES;

    const int e   = blockIdx.z;
    const int cnt = g_counts[e];
    const int mT  = (MODE == 0) ? blockIdx.x : blockIdx.y;
    if (mT * 128 >= cnt) return;
    const int nT  = (MODE == 0) ? blockIdx.y : blockIdx.x;
    const int off = g_offsets[e];
    const int nb  = nT * 128;

    extern __shared__ char dsm[];
    const uint32_t ab = (uint32_t)__cvta_generic_to_shared(dsm);

    const int tid = threadIdx.x;
    const int warp = tid >> 5, lane = tid & 31;

    const __half* Ah = (MODE == 0) ? gXh : gH;
    const __half* Al = gXl;                                // mode0 only
    const __half* Bh = ((MODE == 0) ? gW1h : gW2h) + (size_t)e * DDIM * HDIM;
    const __half* Bl = ((MODE == 0) ? gW1l : gW2l) + (size_t)e * DDIM * HDIM;

    // per-thread cp.async slots: A 4 rows x 16B, B 4 rows x 16B
    const int aC = tid & 7;            // 16B chunk in 128B row
    const int aR = tid >> 3;           // 0..31
    size_t   aSrc[4]; uint32_t aDst[4];
#pragma unroll
    for (int i = 0; i < 4; i++) {
        int r  = aR + i * 32;
        int rm = min(mT * 128 + r, cnt - 1);
        size_t rowbase;
        if (MODE == 0) rowbase = (size_t)(g_tl[off + rm] >> 1) * DDIM;
        else           rowbase = (size_t)(off + rm) * HDIM;
        aSrc[i] = rowbase + aC * 8;
        aDst[i] = (uint32_t)(r * 144 + aC * 16);
    }
    const int bC = tid & 15;           // 16B chunk in 256B row
    const int bR = tid >> 4;           // 0..15
    size_t   bSrc[4]; uint32_t bDst[4];
#pragma unroll
    for (int i = 0; i < 4; i++) {
        int r = bR + i * 16;
        bSrc[i] = (size_t)r * NGL + nb + bC * 8;
        bDst[i] = (uint32_t)(r * 272 + bC * 16);
    }

    auto ldc = [&](int c) {
        uint32_t sb = ab + (uint32_t)(c % NSTAGE) * STG;
        int k0 = c * 64;
#pragma unroll
        for (int i = 0; i < 4; i++) {
            cpa16(sb + aDst[i], Ah + aSrc[i] + k0);
            if (MODE == 0) cpa16(sb + OFF_AL + aDst[i], Al + aSrc[i] + k0);
        }
        size_t bk = (size_t)k0 * NGL;
#pragma unroll
        for (int i = 0; i < 4; i++) {
            cpa16(sb + OFF_BH + bDst[i], Bh + bSrc[i] + bk);
            cpa16(sb + OFF_BL + bDst[i], Bl + bSrc[i] + bk);
        }
        cpa_commit();
    };

    ldc(0);
    ldc(1);

    const int wm = (warp >> 1) * 32;   // 4x2 warp grid -> 32x64 warp tile
    const int wn = (warp & 1) * 64;

    float acc[2][8][4];
#pragma unroll
    for (int a = 0; a < 2; a++)
#pragma unroll
        for (int b = 0; b < 8; b++)
#pragma unroll
            for (int c = 0; c < 4; c++) acc[a][b][c] = 0.f;

    const int aRow  = lane & 15;
    const int aCol  = (lane >> 4) << 3;
    const int bRowL = ((lane >> 3) & 1) * 8 + (lane & 7);
    const int bColL = (lane >> 4) * 8;

    for (int c = 0; c < NC; c++) {
        cpa_wait1();
        __syncthreads();
        if (c + 2 < NC) ldc(c + 2); else cpa_commit();

        uint32_t sb = ab + (uint32_t)(c % NSTAGE) * STG;
#pragma unroll
        for (int ks = 0; ks < 4; ks++) {
            // A fragments
            uint32_t afh[2][4];
#pragma unroll
            for (int ms = 0; ms < 2; ms++)
                ldsm4(afh[ms], sb + (uint32_t)((wm + ms * 16 + aRow) * 144 +
                                               (ks * 16 + aCol) * 2));
            uint32_t afl[2][4];
            if (MODE == 0) {
#pragma unroll
                for (int ms = 0; ms < 2; ms++)
                    ldsm4(afl[ms], sb + OFF_AL +
                          (uint32_t)((wm + ms * 16 + aRow) * 144 +
                                     (ks * 16 + aCol) * 2));
            }
            // B fragments (hi and lo)
            uint32_t bfh[8][2], bfl[8][2];
#pragma unroll
            for (int g = 0; g < 4; g++) {
                uint32_t q[4];
                ldsm4t(q, sb + OFF_BH + (uint32_t)((ks * 16 + bRowL) * 272 +
                                                   (wn + g * 16 + bColL) * 2));
                bfh[g * 2 + 0][0] = q[0]; bfh[g * 2 + 0][1] = q[1];
                bfh[g * 2 + 1][0] = q[2]; bfh[g * 2 + 1][1] = q[3];
                ldsm4t(q, sb + OFF_BL + (uint32_t)((ks * 16 + bRowL) * 272 +
                                                   (wn + g * 16 + bColL) * 2));
                bfl[g * 2 + 0][0] = q[0]; bfl[g * 2 + 0][1] = q[1];
                bfl[g * 2 + 1][0] = q[2]; bfl[g * 2 + 1][1] = q[3];
            }

            // term-major: consecutive mmas hit DIFFERENT accumulators
#pragma unroll
            for (int ms = 0; ms < 2; ms++)
#pragma unroll
                for (int ns = 0; ns < 8; ns++)
                    mma16816(acc[ms][ns], afh[ms], bfh[ns]);   // hi*hi
#pragma unroll
            for (int ms = 0; ms < 2; ms++)
#pragma unroll
                for (int ns = 0; ns < 8; ns++)
                    mma16816(acc[ms][ns], afh[ms], bfl[ns]);   // hi*lo
            if (MODE == 0) {
#pragma unroll
                for (int ms = 0; ms < 2; ms++)
#pragma unroll
                    for (int ns = 0; ns < 8; ns++)
                        mma16816(acc[ms][ns], afl[ms], bfh[ns]); // lo*hi
            }
        }
    }

    // ---------------- epilogue ----------------
#pragma unroll
    for (int ms = 0; ms < 2; ms++) {
        int r0 = wm + ms * 16 + (lane >> 2);
#pragma unroll
        for (int half = 0; half < 2; half++) {
            int r  = r0 + half * 8;
            int gm = mT * 128 + r;
            if (gm < cnt) {
                int idx = off + gm;
                if (MODE == 0) {
                    __half* oh = gH + (size_t)idx * HDIM + nb;
#pragma unroll
                    for (int ns = 0; ns < 8; ns++) {
                        int cc  = wn + ns * 8 + (lane & 3) * 2;
                        float v0 = fmaxf(acc[ms][ns][half * 2 + 0], 0.f);
                        float v1 = fmaxf(acc[ms][ns][half * 2 + 1], 0.f);
                        v0 *= v0; v1 *= v1;
                        *(uint32_t*)(oh + cc) = hpack2(v0, v1);
                    }
                } else {
                    int   pr = g_tl[idx];
                    float gt = g_gl[idx];
                    float* yo = g_ys + (size_t)pr * DDIM + nb;
#pragma unroll
                    for (int ns = 0; ns < 8; ns++) {
                        int cc = wn + ns * 8 + (lane & 3) * 2;
                        *(float2*)(yo + cc) =
                            make_float2(acc[ms][ns][half * 2 + 0] * gt,
                                        acc[ms][ns][half * 2 + 1] * gt);
                    }
                }
            }
        }
    }
}

__global__ void combine_kernel(float* __restrict__ out) {
    size_t i = (size_t)blockIdx.x * blockDim.x + threadIdx.x;  // float4 idx
    const float4* ys = (const float4*)g_ys;
    size_t t = i >> 8;
    size_t d = i & 255;
    float4 a = ys[(t * 2 + 0) * 256 + d];
    float4 b = ys[(t * 2 + 1) * 256 + d];
    ((float4*)out)[i] = make_float4(a.x + b.x, a.y + b.y, a.z + b.z, a.w + b.w);
}

// ---------------- launcher ----------------
extern "C" void kernel_launch(void* const* d_in, const int* in_sizes, int n_in,
                              void* d_out, int out_size) {
    const float* x  = (const float*)d_in[0];
    const float* nz = (const float*)d_in[1];
    const float* Wr = (const float*)d_in[2];
    const float* Wn = (const float*)d_in[3];
    const float* W1 = (const float*)d_in[4];
    const float* W2 = (const float*)d_in[5];
    float* out = (float*)d_out;

    constexpr int DS0 = NSTAGE * (2 * A_BYTES + 2 * B_BYTES);  // 215040
    constexpr int DS1 = NSTAGE * (A_BYTES + 2 * B_BYTES);      // 159744
    cudaFuncSetAttribute(moe_mma<0>, cudaFuncAttributeMaxDynamicSharedMemorySize, DS0);
    cudaFuncSetAttribute(moe_mma<1>, cudaFuncAttributeMaxDynamicSharedMemorySize, DS1);

    zero_meta_kernel<<<1, 32>>>();                                   // 1
    prep_kernel<<<PB_RT, 256>>>(x, nz, Wr, Wn, W1, W2);              // 2
    scanbuild_kernel<<<1, 1024>>>();                                 // 3
    // 4 (profiled): GEMM1  M=cnt N=4096 K=1024
    moe_mma<0><<<dim3(NTOK / 128, HDIM / 128, NEXP), 256, DS0>>>();
    // 5: GEMM2  M=cnt N=1024 K=4096
    moe_mma<1><<<dim3(DDIM / 128, NTOK / 128, NEXP), 256, DS1>>>();
    combine_kernel<<<(NTOK * DDIM / 4) / 256, 256>>>(out);           // 6
}

// round 5
// speedup vs baseline: 1.4411x; 1.0000x over previous
#include <cuda_runtime.h>
#include <cuda_fp16.h>
#include <math.h>
#include <stdint.h>

#define NTOK 8192
#define DDIM 1024
#define HDIM 4096
#define NEXP 8
#define NPAIR (NTOK * 2)

// ---------------- scratch (device globals: allocation-free rule) ----------------
__device__ __half gXh[(size_t)NTOK * DDIM];   // fp16 hi of x (token order)
__device__ __half gXl[(size_t)NTOK * DDIM];   // fp16 residual of x
__device__ __half gH[(size_t)NPAIR * HDIM];   // h = relu(u)^2, fp16, grouped
__device__ __half gW1h[(size_t)NEXP * DDIM * HDIM];
__device__ __half gW1l[(size_t)NEXP * DDIM * HDIM];
__device__ __half gW2h[(size_t)NEXP * HDIM * DDIM];
__device__ __half gW2l[(size_t)NEXP * HDIM * DDIM];
__device__ float g_ys[(size_t)NPAIR * DDIM];
__device__ int   g_tl[NPAIR];
__device__ float g_gl[NPAIR];
__device__ int   g_counts[NEXP];
__device__ int   g_offsets[NEXP + 1];
__device__ int   g_cursor[NEXP];
__device__ int   g_tok_e[NTOK];
__device__ float g_tok_g[NTOK * 2];

// ---------------- helpers ----------------
__device__ __forceinline__ uint32_t hpack2(float a, float b) {
    __half2 h = __floats2half2_rn(a, b);
    return *(uint32_t*)&h;
}
__device__ __forceinline__ uint32_t lpack2(float a, float b) {
    float ra = a - __half2float(__float2half_rn(a));
    float rb = b - __half2float(__float2half_rn(b));
    __half2 h = __floats2half2_rn(ra, rb);
    return *(uint32_t*)&h;
}

// ---------------- launch 1: zero meta ----------------
__global__ void zero_meta_kernel() {
    int i = threadIdx.x;
    if (i < NEXP) { g_counts[i] = 0; g_cursor[i] = 0; }
}

// ---------------- launch 2: fused prep (splitW1 | splitW2 | splitX | route) ----
#define PB_W1 32768
#define PB_W2 65536
#define PB_X  73728
#define PB_RT 74752

__global__ __launch_bounds__(256)
void prep_kernel(const float* __restrict__ x, const float* __restrict__ noisep,
                 const float* __restrict__ Wr, const float* __restrict__ Wn,
                 const float* __restrict__ W1, const float* __restrict__ W2) {
    int b = blockIdx.x, tid = threadIdx.x;
    if (b < PB_W2) {
        const float* W = (b < PB_W1) ? W1 : W2;
        __half* oh = (b < PB_W1) ? gW1h : gW2h;
        __half* ol = (b < PB_W1) ? gW1l : gW2l;
        size_t i = ((size_t)(b < PB_W1 ? b : b - PB_W1) * 256 + tid);
        float4 v = ((const float4*)W)[i];
        *(uint2*)(oh + i * 4) = make_uint2(hpack2(v.x, v.y), hpack2(v.z, v.w));
        *(uint2*)(ol + i * 4) = make_uint2(lpack2(v.x, v.y), lpack2(v.z, v.w));
    } else if (b < PB_X) {
        int t = b - PB_W2;
        float4 v = ((const float4*)(x + (size_t)t * DDIM))[tid];
        size_t o = (size_t)t * DDIM + tid * 4;
        *(uint2*)(gXh + o) = make_uint2(hpack2(v.x, v.y), hpack2(v.z, v.w));
        *(uint2*)(gXl + o) = make_uint2(lpack2(v.x, v.y), lpack2(v.z, v.w));
    } else {
        // router: one warp per token
        int warp = tid >> 5, lane = tid & 31;
        int t = (b - PB_X) * 8 + warp;
        const float* xr = x + (size_t)t * DDIM;
        float xs[32];
#pragma unroll
        for (int i = 0; i < 32; i++) xs[i] = xr[lane + 32 * i];
        float nz[NEXP];
#pragma unroll
        for (int e = 0; e < NEXP; e++) {
            const float* wr = Wr + e * DDIM;
            const float* wn = Wn + e * DDIM;
            float a = 0.f, bb = 0.f;
#pragma unroll
            for (int i = 0; i < 32; i++) {
                float xv = xs[i];
                a  = fmaf(xv, wr[lane + 32 * i], a);
                bb = fmaf(xv, wn[lane + 32 * i], bb);
            }
#pragma unroll
            for (int o = 16; o > 0; o >>= 1) {
                a  += __shfl_xor_sync(0xffffffffu, a, o);
                bb += __shfl_xor_sync(0xffffffffu, bb, o);
            }
            float sp = fmaxf(bb, 0.f) + log1pf(expf(-fabsf(bb)));
            nz[e] = a + noisep[t * NEXP + e] * sp;
        }
        if (lane == 0) {
            int e0 = 0; float v0 = nz[0];
#pragma unroll
            for (int e = 1; e < NEXP; e++) if (nz[e] > v0) { v0 = nz[e]; e0 = e; }
            int e1 = (e0 == 0) ? 1 : 0; float v1 = nz[e1];
#pragma unroll
            for (int e = 0; e < NEXP; e++)
                if (e != e0 && nz[e] > v1) { v1 = nz[e]; e1 = e; }
            float m  = fmaxf(v0, v1);
            float z0 = expf(v0 - m), z1 = expf(v1 - m);
            float inv = 1.f / (z0 + z1);
            g_tok_e[t] = e0 | (e1 << 8);
            g_tok_g[t * 2 + 0] = z0 * inv;
            g_tok_g[t * 2 + 1] = z1 * inv;
            atomicAdd(&g_counts[e0], 1);
            atomicAdd(&g_counts[e1], 1);
        }
    }
}

// ---------------- launch 3: scan + build (single CTA) ----------------
__global__ void scanbuild_kernel() {
    int tid = threadIdx.x;
    if (tid == 0) {
        int s = 0;
        for (int e = 0; e < NEXP; e++) { g_offsets[e] = s; s += g_counts[e]; }
        g_offsets[NEXP] = s;
    }
    __syncthreads();
    for (int t = tid; t < NTOK; t += 1024) {
        int ee = g_tok_e[t];
        int e0 = ee & 0xff, e1 = ee >> 8;
        int s  = atomicAdd(&g_cursor[e0], 1);
        int i0 = g_offsets[e0] + s;
        g_tl[i0] = t * 2;     g_gl[i0] = g_tok_g[t * 2];
        s = atomicAdd(&g_cursor[e1], 1);
        int i1 = g_offsets[e1] + s;
        g_tl[i1] = t * 2 + 1; g_gl[i1] = g_tok_g[t * 2 + 1];
    }
}

// ---------------- mma helpers ----------------
__device__ __forceinline__ void ldsm4(uint32_t (&r)[4], uint32_t a) {
    asm volatile("ldmatrix.sync.aligned.m8n8.x4.shared.b16 {%0,%1,%2,%3}, [%4];\n"
                 : "=r"(r[0]), "=r"(r[1]), "=r"(r[2]), "=r"(r[3]) : "r"(a));
}
__device__ __forceinline__ void ldsm4t(uint32_t (&r)[4], uint32_t a) {
    asm volatile("ldmatrix.sync.aligned.m8n8.x4.trans.shared.b16 {%0,%1,%2,%3}, [%4];\n"
                 : "=r"(r[0]), "=r"(r[1]), "=r"(r[2]), "=r"(r[3]) : "r"(a));
}
__device__ __forceinline__ void mma16816(float (&c)[4], const uint32_t (&a)[4],
                                         const uint32_t (&b)[2]) {
    asm volatile(
        "mma.sync.aligned.m16n8k16.row.col.f32.f16.f16.f32 "
        "{%0,%1,%2,%3},{%4,%5,%6,%7},{%8,%9},{%0,%1,%2,%3};\n"
        : "+f"(c[0]), "+f"(c[1]), "+f"(c[2]), "+f"(c[3])
        : "r"(a[0]), "r"(a[1]), "r"(a[2]), "r"(a[3]), "r"(b[0]), "r"(b[1]));
}
__device__ __forceinline__ void cpa16(uint32_t d, const void* s) {
    asm volatile("cp.async.cg.shared.global [%0], [%1], 16;" :: "r"(d), "l"(s)
                 : "memory");
}
__device__ __forceinline__ void cpa_commit() {
    asm volatile("cp.async.commit_group;" ::: "memory");
}
__device__ __forceinline__ void cpa_wait1() {
    asm volatile("cp.async.wait_group 1;" ::: "memory");
}

// smem geometry: BK=64. A rows 144B pitch (72 halves), B rows 272B pitch (136 halves).
#define A_BYTES 18432
#define B_BYTES 17408
#define NSTAGE 3

// ---------------- grouped split-fp16 mma.sync GEMM ----------------
// MODE 0 (launch 4): h = relu(x @ W1[e])^2 -> gH (fp16)   K=1024 N=4096, 3 terms
// MODE 1 (launch 5): ys = gate * (h @ W2[e]) -> g_ys      K=4096 N=1024, 2 terms
template <int MODE>
__global__ __launch_bounds__(256, 1)
void moe_mma() {
    constexpr int K      = (MODE == 0) ? DDIM : HDIM;
    constexpr int NGL    = (MODE == 0) ? HDIM : DDIM;
    constexpr int NC     = K / 64;
    constexpr int OFF_AL = A_BYTES;                       // mode0 only
    constexpr int OFF_BH = (MODE == 0) ? 2 * A_BYTES : A_BYTES;
    constexpr int OFF_BL = OFF_BH + B_BYTES;
    constexpr int STG    = OFF_BL + B_BYTES;

    const int e   = blockIdx.z;
    const int cnt = g_counts[e];
    const int mT  = (MODE == 0) ? blockIdx.x : blockIdx.y;
    if (mT * 128 >= cnt) return;
    const int nT  = (MODE == 0) ? blockIdx.y : blockIdx.x;
    const int off = g_offsets[e];
    const int nb  = nT * 128;

    extern __shared__ char dsm[];
    const uint32_t ab = (uint32_t)__cvta_generic_to_shared(dsm);

    const int tid = threadIdx.x;
    const int warp = tid >> 5, lane = tid & 31;

    const __half* Ah = (MODE == 0) ? gXh : gH;
    const __half* Al = gXl;                                // mode0 only
    const __half* Bh = ((MODE == 0) ? gW1h : gW2h) + (size_t)e * DDIM * HDIM;
    const __half* Bl = ((MODE == 0) ? gW1l : gW2l) + (size_t)e * DDIM * HDIM;

    // per-thread cp.async slots: A 4 rows x 16B, B 4 rows x 16B
    const int aC = tid & 7;            // 16B chunk in 128B row
    const int aR = tid >> 3;           // 0..31
    size_t   aSrc[4]; uint32_t aDst[4];
#pragma unroll
    for (int i = 0; i < 4; i++) {
        int r  = aR + i * 32;
        int rm = min(mT * 128 + r, cnt - 1);
        size_t rowbase;
        if (MODE == 0) rowbase = (size_t)(g_tl[off + rm] >> 1) * DDIM;
        else           rowbase = (size_t)(off + rm) * HDIM;
        aSrc[i] = rowbase + aC * 8;
        aDst[i] = (uint32_t)(r * 144 + aC * 16);
    }
    const int bC = tid & 15;           // 16B chunk in 256B row
    const int bR = tid >> 4;           // 0..15
    size_t   bSrc[4]; uint32_t bDst[4];
#pragma unroll
    for (int i = 0; i < 4; i++) {
        int r = bR + i * 16;
        bSrc[i] = (size_t)r * NGL + nb + bC * 8;
        bDst[i] = (uint32_t)(r * 272 + bC * 16);
    }

    auto ldc = [&](int c) {
        uint32_t sb = ab + (uint32_t)(c % NSTAGE) * STG;
        int k0 = c * 64;
#pragma unroll
        for (int i = 0; i < 4; i++) {
            cpa16(sb + aDst[i], Ah + aSrc[i] + k0);
            if (MODE == 0) cpa16(sb + OFF_AL + aDst[i], Al + aSrc[i] + k0);
        }
        size_t bk = (size_t)k0 * NGL;
#pragma unroll
        for (int i = 0; i < 4; i++) {
            cpa16(sb + OFF_BH + bDst[i], Bh + bSrc[i] + bk);
            cpa16(sb + OFF_BL + bDst[i], Bl + bSrc[i] + bk);
        }
        cpa_commit();
    };

    ldc(0);
    ldc(1);

    const int wm = (warp >> 1) * 32;   // 4x2 warp grid -> 32x64 warp tile
    const int wn = (warp & 1) * 64;

    float acc[2][8][4];
#pragma unroll
    for (int a = 0; a < 2; a++)
#pragma unroll
        for (int b = 0; b < 8; b++)
#pragma unroll
            for (int c = 0; c < 4; c++) acc[a][b][c] = 0.f;

    const int aRow  = lane & 15;
    const int aCol  = (lane >> 4) << 3;
    const int bRowL = ((lane >> 3) & 1) * 8 + (lane & 7);
    const int bColL = (lane >> 4) * 8;

    // double-buffered register fragments: prefetch ks+1 while ks's MMAs run
    uint32_t afh[2][2][4];
    uint32_t afl[2][2][4];
    uint32_t bfh[2][8][2], bfl[2][8][2];

    auto ldfrag = [&](int bf, int ks, uint32_t sb) {
#pragma unroll
        for (int ms = 0; ms < 2; ms++)
            ldsm4(afh[bf][ms], sb + (uint32_t)((wm + ms * 16 + aRow) * 144 +
                                               (ks * 16 + aCol) * 2));
        if (MODE == 0) {
#pragma unroll
            for (int ms = 0; ms < 2; ms++)
                ldsm4(afl[bf][ms], sb + OFF_AL +
                      (uint32_t)((wm + ms * 16 + aRow) * 144 +
                                 (ks * 16 + aCol) * 2));
        }
#pragma unroll
        for (int g = 0; g < 4; g++) {
            uint32_t q[4];
            ldsm4t(q, sb + OFF_BH + (uint32_t)((ks * 16 + bRowL) * 272 +
                                               (wn + g * 16 + bColL) * 2));
            bfh[bf][g * 2 + 0][0] = q[0]; bfh[bf][g * 2 + 0][1] = q[1];
            bfh[bf][g * 2 + 1][0] = q[2]; bfh[bf][g * 2 + 1][1] = q[3];
            ldsm4t(q, sb + OFF_BL + (uint32_t)((ks * 16 + bRowL) * 272 +
                                               (wn + g * 16 + bColL) * 2));
            bfl[bf][g * 2 + 0][0] = q[0]; bfl[bf][g * 2 + 0][1] = q[1];
            bfl[bf][g * 2 + 1][0] = q[2]; bfl[bf][g * 2 + 1][1] = q[3];
        }
    };

    for (int c = 0; c < NC; c++) {
        cpa_wait1();
        __syncthreads();
        if (c + 2 < NC) ldc(c + 2); else cpa_commit();

        uint32_t sb = ab + (uint32_t)(c % NSTAGE) * STG;
        ldfrag(0, 0, sb);
#pragma unroll
        for (int ks = 0; ks < 4; ks++) {
            const int cur = ks & 1;
            if (ks < 3) ldfrag((ks + 1) & 1, ks + 1, sb);

            // term-major: consecutive mmas hit DIFFERENT accumulators
#pragma unroll
            for (int ms = 0; ms < 2; ms++)
#pragma unroll
                for (int ns = 0; ns < 8; ns++)
                    mma16816(acc[ms][ns], afh[cur][ms], bfh[cur][ns]);  // hi*hi
#pragma unroll
            for (int ms = 0; ms < 2; ms++)
#pragma unroll
                for (int ns = 0; ns < 8; ns++)
                    mma16816(acc[ms][ns], afh[cur][ms], bfl[cur][ns]);  // hi*lo
            if (MODE == 0) {
#pragma unroll
                for (int ms = 0; ms < 2; ms++)
#pragma unroll
                    for (int ns = 0; ns < 8; ns++)
                        mma16816(acc[ms][ns], afl[cur][ms], bfh[cur][ns]); // lo*hi
            }
        }
    }

    // ---------------- epilogue ----------------
#pragma unroll
    for (int ms = 0; ms < 2; ms++) {
        int r0 = wm + ms * 16 + (lane >> 2);
#pragma unroll
        for (int half = 0; half < 2; half++) {
            int r  = r0 + half * 8;
            int gm = mT * 128 + r;
            if (gm < cnt) {
                int idx = off + gm;
                if (MODE == 0) {
                    __half* oh = gH + (size_t)idx * HDIM + nb;
#pragma unroll
                    for (int ns = 0; ns < 8; ns++) {
                        int cc  = wn + ns * 8 + (lane & 3) * 2;
                        float v0 = fmaxf(acc[ms][ns][half * 2 + 0], 0.f);
                        float v1 = fmaxf(acc[ms][ns][half * 2 + 1], 0.f);
                        v0 *= v0; v1 *= v1;
                        *(uint32_t*)(oh + cc) = hpack2(v0, v1);
                    }
                } else {
                    int   pr = g_tl[idx];
                    float gt = g_gl[idx];
                    float* yo = g_ys + (size_t)pr * DDIM + nb;
#pragma unroll
                    for (int ns = 0; ns < 8; ns++) {
                        int cc = wn + ns * 8 + (lane & 3) * 2;
                        *(float2*)(yo + cc) =
                            make_float2(acc[ms][ns][half * 2 + 0] * gt,
                                        acc[ms][ns][half * 2 + 1] * gt);
                    }
                }
            }
        }
    }
}

__global__ void combine_kernel(float* __restrict__ out) {
    size_t i = (size_t)blockIdx.x * blockDim.x + threadIdx.x;  // float4 idx
    const float4* ys = (const float4*)g_ys;
    size_t t = i >> 8;
    size_t d = i & 255;
    float4 a = ys[(t * 2 + 0) * 256 + d];
    float4 b = ys[(t * 2 + 1) * 256 + d];
    ((float4*)out)[i] = make_float4(a.x + b.x, a.y + b.y, a.z + b.z, a.w + b.w);
}

// ---------------- launcher ----------------
extern "C" void kernel_launch(void* const* d_in, const int* in_sizes, int n_in,
                              void* d_out, int out_size) {
    const float* x  = (const float*)d_in[0];
    const float* nz = (const float*)d_in[1];
    const float* Wr = (const float*)d_in[2];
    const float* Wn = (const float*)d_in[3];
    const float* W1 = (const float*)d_in[4];
    const float* W2 = (const float*)d_in[5];
    float* out = (float*)d_out;

    constexpr int DS0 = NSTAGE * (2 * A_BYTES + 2 * B_BYTES);  // 215040
    constexpr int DS1 = NSTAGE * (A_BYTES + 2 * B_BYTES);      // 159744
    cudaFuncSetAttribute(moe_mma<0>, cudaFuncAttributeMaxDynamicSharedMemorySize, DS0);
    cudaFuncSetAttribute(moe_mma<1>, cudaFuncAttributeMaxDynamicSharedMemorySize, DS1);

    zero_meta_kernel<<<1, 32>>>();                                   // 1
    prep_kernel<<<PB_RT, 256>>>(x, nz, Wr, Wn, W1, W2);              // 2
    scanbuild_kernel<<<1, 1024>>>();                                 // 3
    // 4 (profiled): GEMM1  M=cnt N=4096 K=1024
    moe_mma<0><<<dim3(NTOK / 128, HDIM / 128, NEXP), 256, DS0>>>();
    // 5: GEMM2  M=cnt N=1024 K=4096
    moe_mma<1><<<dim3(DDIM / 128, NTOK / 128, NEXP), 256, DS1>>>();
    combine_kernel<<<(NTOK * DDIM / 4) / 256, 256>>>(out);           // 6
}

// round 6
// speedup vs baseline: 1.6793x; 1.1653x over previous
#include <cuda_runtime.h>
#include <cuda_fp16.h>
#include <math.h>
#include <stdint.h>

#define NTOK 8192
#define DDIM 1024
#define HDIM 4096
#define NEXP 8
#define NPAIR (NTOK * 2)

// ---------------- scratch (device globals: allocation-free rule) ----------------
__device__ __half gXh[(size_t)NTOK * DDIM];   // fp16 hi of x (token order)
__device__ __half gXl[(size_t)NTOK * DDIM];   // fp16 residual of x
__device__ __half gH[(size_t)NPAIR * HDIM];   // h = relu(u)^2, fp16, grouped
__device__ __half gW1h[(size_t)NEXP * DDIM * HDIM];
__device__ __half gW1l[(size_t)NEXP * DDIM * HDIM];
__device__ __half gW2h[(size_t)NEXP * HDIM * DDIM];
__device__ float g_ys[(size_t)NPAIR * DDIM];
__device__ int   g_tl[NPAIR];
__device__ float g_gl[NPAIR];
__device__ int   g_counts[NEXP];
__device__ int   g_offsets[NEXP + 1];
__device__ int   g_cursor[NEXP];
__device__ int   g_tok_e[NTOK];
__device__ float g_tok_g[NTOK * 2];

// ---------------- helpers ----------------
__device__ __forceinline__ uint32_t hpack2(float a, float b) {
    __half2 h = __floats2half2_rn(a, b);
    return *(uint32_t*)&h;
}
__device__ __forceinline__ uint32_t lpack2(float a, float b) {
    float ra = a - __half2float(__float2half_rn(a));
    float rb = b - __half2float(__float2half_rn(b));
    __half2 h = __floats2half2_rn(ra, rb);
    return *(uint32_t*)&h;
}

// ---------------- launch 1: zero meta ----------------
__global__ void zero_meta_kernel() {
    int i = threadIdx.x;
    if (i < NEXP) { g_counts[i] = 0; g_cursor[i] = 0; }
}

// ---------------- launch 2: fused prep (splitW1 | W2 hi | splitX | route) ----
#define PB_W1 32768
#define PB_W2 65536
#define PB_X  73728
#define PB_RT 74752

__global__ __launch_bounds__(256)
void prep_kernel(const float* __restrict__ x, const float* __restrict__ noisep,
                 const float* __restrict__ Wr, const float* __restrict__ Wn,
                 const float* __restrict__ W1, const float* __restrict__ W2) {
    int b = blockIdx.x, tid = threadIdx.x;
    if (b < PB_W1) {
        size_t i = ((size_t)b * 256 + tid);
        float4 v = ((const float4*)W1)[i];
        *(uint2*)(gW1h + i * 4) = make_uint2(hpack2(v.x, v.y), hpack2(v.z, v.w));
        *(uint2*)(gW1l + i * 4) = make_uint2(lpack2(v.x, v.y), lpack2(v.z, v.w));
    } else if (b < PB_W2) {
        size_t i = ((size_t)(b - PB_W1) * 256 + tid);
        float4 v = ((const float4*)W2)[i];
        *(uint2*)(gW2h + i * 4) = make_uint2(hpack2(v.x, v.y), hpack2(v.z, v.w));
    } else if (b < PB_X) {
        int t = b - PB_W2;
        float4 v = ((const float4*)(x + (size_t)t * DDIM))[tid];
        size_t o = (size_t)t * DDIM + tid * 4;
        *(uint2*)(gXh + o) = make_uint2(hpack2(v.x, v.y), hpack2(v.z, v.w));
        *(uint2*)(gXl + o) = make_uint2(lpack2(v.x, v.y), lpack2(v.z, v.w));
    } else {
        // router: one warp per token
        int warp = tid >> 5, lane = tid & 31;
        int t = (b - PB_X) * 8 + warp;
        const float* xr = x + (size_t)t * DDIM;
        float xs[32];
#pragma unroll
        for (int i = 0; i < 32; i++) xs[i] = xr[lane + 32 * i];
        float nz[NEXP];
#pragma unroll
        for (int e = 0; e < NEXP; e++) {
            const float* wr = Wr + e * DDIM;
            const float* wn = Wn + e * DDIM;
            float a = 0.f, bb = 0.f;
#pragma unroll
            for (int i = 0; i < 32; i++) {
                float xv = xs[i];
                a  = fmaf(xv, wr[lane + 32 * i], a);
                bb = fmaf(xv, wn[lane + 32 * i], bb);
            }
#pragma unroll
            for (int o = 16; o > 0; o >>= 1) {
                a  += __shfl_xor_sync(0xffffffffu, a, o);
                bb += __shfl_xor_sync(0xffffffffu, bb, o);
            }
            float sp = fmaxf(bb, 0.f) + log1pf(expf(-fabsf(bb)));
            nz[e] = a + noisep[t * NEXP + e] * sp;
        }
        if (lane == 0) {
            int e0 = 0; float v0 = nz[0];
#pragma unroll
            for (int e = 1; e < NEXP; e++) if (nz[e] > v0) { v0 = nz[e]; e0 = e; }
            int e1 = (e0 == 0) ? 1 : 0; float v1 = nz[e1];
#pragma unroll
            for (int e = 0; e < NEXP; e++)
                if (e != e0 && nz[e] > v1) { v1 = nz[e]; e1 = e; }
            float m  = fmaxf(v0, v1);
            float z0 = expf(v0 - m), z1 = expf(v1 - m);
            float inv = 1.f / (z0 + z1);
            g_tok_e[t] = e0 | (e1 << 8);
            g_tok_g[t * 2 + 0] = z0 * inv;
            g_tok_g[t * 2 + 1] = z1 * inv;
            atomicAdd(&g_counts[e0], 1);
            atomicAdd(&g_counts[e1], 1);
        }
    }
}

// ---------------- launch 3: scan + build (single CTA) ----------------
__global__ void scanbuild_kernel() {
    int tid = threadIdx.x;
    if (tid == 0) {
        int s = 0;
        for (int e = 0; e < NEXP; e++) { g_offsets[e] = s; s += g_counts[e]; }
        g_offsets[NEXP] = s;
    }
    __syncthreads();
    for (int t = tid; t < NTOK; t += 1024) {
        int ee = g_tok_e[t];
        int e0 = ee & 0xff, e1 = ee >> 8;
        int s  = atomicAdd(&g_cursor[e0], 1);
        int i0 = g_offsets[e0] + s;
        g_tl[i0] = t * 2;     g_gl[i0] = g_tok_g[t * 2];
        s = atomicAdd(&g_cursor[e1], 1);
        int i1 = g_offsets[e1] + s;
        g_tl[i1] = t * 2 + 1; g_gl[i1] = g_tok_g[t * 2 + 1];
    }
}

// ---------------- mma helpers ----------------
__device__ __forceinline__ void ldsm4(uint32_t (&r)[4], uint32_t a) {
    asm volatile("ldmatrix.sync.aligned.m8n8.x4.shared.b16 {%0,%1,%2,%3}, [%4];\n"
                 : "=r"(r[0]), "=r"(r[1]), "=r"(r[2]), "=r"(r[3]) : "r"(a));
}
__device__ __forceinline__ void ldsm4t(uint32_t (&r)[4], uint32_t a) {
    asm volatile("ldmatrix.sync.aligned.m8n8.x4.trans.shared.b16 {%0,%1,%2,%3}, [%4];\n"
                 : "=r"(r[0]), "=r"(r[1]), "=r"(r[2]), "=r"(r[3]) : "r"(a));
}
__device__ __forceinline__ void mma16816(float (&c)[4], const uint32_t (&a)[4],
                                         const uint32_t (&b)[2]) {
    asm volatile(
        "mma.sync.aligned.m16n8k16.row.col.f32.f16.f16.f32 "
        "{%0,%1,%2,%3},{%4,%5,%6,%7},{%8,%9},{%0,%1,%2,%3};\n"
        : "+f"(c[0]), "+f"(c[1]), "+f"(c[2]), "+f"(c[3])
        : "r"(a[0]), "r"(a[1]), "r"(a[2]), "r"(a[3]), "r"(b[0]), "r"(b[1]));
}
__device__ __forceinline__ void cpa16(uint32_t d, const void* s) {
    asm volatile("cp.async.cg.shared.global [%0], [%1], 16;" :: "r"(d), "l"(s)
                 : "memory");
}
__device__ __forceinline__ void cpa_commit() {
    asm volatile("cp.async.commit_group;" ::: "memory");
}
__device__ __forceinline__ void cpa_wait1() {
    asm volatile("cp.async.wait_group 1;" ::: "memory");
}

// smem geometry: BK=64. A rows 144B pitch (72 halves), B rows 272B pitch (136 halves).
#define A_BYTES 18432
#define B_BYTES 17408
#define NSTAGE 3

// ---------------- grouped split-fp16 mma.sync GEMM ----------------
// MODE 0 (launch 4): h = relu(x @ W1[e])^2 -> gH (fp16)   K=1024 N=4096, 3 terms
// MODE 1 (launch 5): ys = gate * (h @ W2[e]) -> g_ys      K=4096 N=1024, 1 term
template <int MODE>
__global__ __launch_bounds__(256, 1)
void moe_mma() {
    constexpr int K      = (MODE == 0) ? DDIM : HDIM;
    constexpr int NGL    = (MODE == 0) ? HDIM : DDIM;
    constexpr int NC     = K / 64;
    constexpr int OFF_AL = A_BYTES;                         // mode0 only
    constexpr int OFF_BH = (MODE == 0) ? 2 * A_BYTES : A_BYTES;
    constexpr int OFF_BL = OFF_BH + B_BYTES;                // mode0 only
    constexpr int STG    = (MODE == 0) ? OFF_BL + B_BYTES : OFF_BH + B_BYTES;

    const int e   = blockIdx.z;
    const int cnt = g_counts[e];
    const int mT  = (MODE == 0) ? blockIdx.x : blockIdx.y;
    if (mT * 128 >= cnt) return;
    const int nT  = (MODE == 0) ? blockIdx.y : blockIdx.x;
    const int off = g_offsets[e];
    const int nb  = nT * 128;

    extern __shared__ char dsm[];
    const uint32_t ab = (uint32_t)__cvta_generic_to_shared(dsm);

    const int tid = threadIdx.x;
    const int warp = tid >> 5, lane = tid & 31;

    const __half* Ah = (MODE == 0) ? gXh : gH;
    const __half* Al = gXl;                                  // mode0 only
    const __half* Bh = ((MODE == 0) ? gW1h : gW2h) + (size_t)e * DDIM * HDIM;
    const __half* Bl = gW1l + (size_t)e * DDIM * HDIM;       // mode0 only

    // per-thread cp.async slots: A 4 rows x 16B, B 4 rows x 16B
    const int aC = tid & 7;            // 16B chunk in 128B row
    const int aR = tid >> 3;           // 0..31
    size_t   aSrc[4]; uint32_t aDst[4];
#pragma unroll
    for (int i = 0; i < 4; i++) {
        int r  = aR + i * 32;
        int rm = min(mT * 128 + r, cnt - 1);
        size_t rowbase;
        if (MODE == 0) rowbase = (size_t)(g_tl[off + rm] >> 1) * DDIM;
        else           rowbase = (size_t)(off + rm) * HDIM;
        aSrc[i] = rowbase + aC * 8;
        aDst[i] = (uint32_t)(r * 144 + aC * 16);
    }
    const int bC = tid & 15;           // 16B chunk in 256B row
    const int bR = tid >> 4;           // 0..15
    size_t   bSrc[4]; uint32_t bDst[4];
#pragma unroll
    for (int i = 0; i < 4; i++) {
        int r = bR + i * 16;
        bSrc[i] = (size_t)r * NGL + nb + bC * 8;
        bDst[i] = (uint32_t)(r * 272 + bC * 16);
    }

    auto ldc = [&](int c) {
        uint32_t sb = ab + (uint32_t)(c % NSTAGE) * STG;
        int k0 = c * 64;
#pragma unroll
        for (int i = 0; i < 4; i++) {
            cpa16(sb + aDst[i], Ah + aSrc[i] + k0);
            if (MODE == 0) cpa16(sb + OFF_AL + aDst[i], Al + aSrc[i] + k0);
        }
        size_t bk = (size_t)k0 * NGL;
#pragma unroll
        for (int i = 0; i < 4; i++) {
            cpa16(sb + OFF_BH + bDst[i], Bh + bSrc[i] + bk);
            if (MODE == 0) cpa16(sb + OFF_BL + bDst[i], Bl + bSrc[i] + bk);
        }
        cpa_commit();
    };

    ldc(0);
    ldc(1);

    const int wm = (warp >> 1) * 32;   // 4x2 warp grid -> 32x64 warp tile
    const int wn = (warp & 1) * 64;

    float acc[2][8][4];
#pragma unroll
    for (int a = 0; a < 2; a++)
#pragma unroll
        for (int b = 0; b < 8; b++)
#pragma unroll
            for (int c = 0; c < 4; c++) acc[a][b][c] = 0.f;

    const int aRow  = lane & 15;
    const int aCol  = (lane >> 4) << 3;
    const int bRowL = ((lane >> 3) & 1) * 8 + (lane & 7);
    const int bColL = (lane >> 4) * 8;

    // double-buffered register fragments
    uint32_t afh[2][2][4];
    uint32_t afl[2][2][4];
    uint32_t bfh[2][8][2], bfl[2][8][2];

    auto ldfrag = [&](int bf, int ks, uint32_t sb) {
#pragma unroll
        for (int ms = 0; ms < 2; ms++)
            ldsm4(afh[bf][ms], sb + (uint32_t)((wm + ms * 16 + aRow) * 144 +
                                               (ks * 16 + aCol) * 2));
        if (MODE == 0) {
#pragma unroll
            for (int ms = 0; ms < 2; ms++)
                ldsm4(afl[bf][ms], sb + OFF_AL +
                      (uint32_t)((wm + ms * 16 + aRow) * 144 +
                                 (ks * 16 + aCol) * 2));
        }
#pragma unroll
        for (int g = 0; g < 4; g++) {
            uint32_t q[4];
            ldsm4t(q, sb + OFF_BH + (uint32_t)((ks * 16 + bRowL) * 272 +
                                               (wn + g * 16 + bColL) * 2));
            bfh[bf][g * 2 + 0][0] = q[0]; bfh[bf][g * 2 + 0][1] = q[1];
            bfh[bf][g * 2 + 1][0] = q[2]; bfh[bf][g * 2 + 1][1] = q[3];
            if (MODE == 0) {
                ldsm4t(q, sb + OFF_BL + (uint32_t)((ks * 16 + bRowL) * 272 +
                                                   (wn + g * 16 + bColL) * 2));
                bfl[bf][g * 2 + 0][0] = q[0]; bfl[bf][g * 2 + 0][1] = q[1];
                bfl[bf][g * 2 + 1][0] = q[2]; bfl[bf][g * 2 + 1][1] = q[3];
            }
        }
    };

    for (int c = 0; c < NC; c++) {
        cpa_wait1();
        __syncthreads();
        if (c + 2 < NC) ldc(c + 2); else cpa_commit();

        uint32_t sb = ab + (uint32_t)(c % NSTAGE) * STG;
        ldfrag(0, 0, sb);
#pragma unroll
        for (int ks = 0; ks < 4; ks++) {
            const int cur = ks & 1;
            if (ks < 3) ldfrag((ks + 1) & 1, ks + 1, sb);

            // term-major: consecutive mmas hit DIFFERENT accumulators
#pragma unroll
            for (int ms = 0; ms < 2; ms++)
#pragma unroll
                for (int ns = 0; ns < 8; ns++)
                    mma16816(acc[ms][ns], afh[cur][ms], bfh[cur][ns]);  // hi*hi
            if (MODE == 0) {
#pragma unroll
                for (int ms = 0; ms < 2; ms++)
#pragma unroll
                    for (int ns = 0; ns < 8; ns++)
                        mma16816(acc[ms][ns], afh[cur][ms], bfl[cur][ns]); // hi*lo
#pragma unroll
                for (int ms = 0; ms < 2; ms++)
#pragma unroll
                    for (int ns = 0; ns < 8; ns++)
                        mma16816(acc[ms][ns], afl[cur][ms], bfh[cur][ns]); // lo*hi
            }
        }
    }

    // ---------------- epilogue ----------------
#pragma unroll
    for (int ms = 0; ms < 2; ms++) {
        int r0 = wm + ms * 16 + (lane >> 2);
#pragma unroll
        for (int half = 0; half < 2; half++) {
            int r  = r0 + half * 8;
            int gm = mT * 128 + r;
            if (gm < cnt) {
                int idx = off + gm;
                if (MODE == 0) {
                    __half* oh = gH + (size_t)idx * HDIM + nb;
#pragma unroll
                    for (int ns = 0; ns < 8; ns++) {
                        int cc  = wn + ns * 8 + (lane & 3) * 2;
                        float v0 = fmaxf(acc[ms][ns][half * 2 + 0], 0.f);
                        float v1 = fmaxf(acc[ms][ns][half * 2 + 1], 0.f);
                        v0 *= v0; v1 *= v1;
                        *(uint32_t*)(oh + cc) = hpack2(v0, v1);
                    }
                } else {
                    int   pr = g_tl[idx];
                    float gt = g_gl[idx];
                    float* yo = g_ys + (size_t)pr * DDIM + nb;
#pragma unroll
                    for (int ns = 0; ns < 8; ns++) {
                        int cc = wn + ns * 8 + (lane & 3) * 2;
                        *(float2*)(yo + cc) =
                            make_float2(acc[ms][ns][half * 2 + 0] * gt,
                                        acc[ms][ns][half * 2 + 1] * gt);
                    }
                }
            }
        }
    }
}

__global__ void combine_kernel(float* __restrict__ out) {
    size_t i = (size_t)blockIdx.x * blockDim.x + threadIdx.x;  // float4 idx
    const float4* ys = (const float4*)g_ys;
    size_t t = i >> 8;
    size_t d = i & 255;
    float4 a = ys[(t * 2 + 0) * 256 + d];
    float4 b = ys[(t * 2 + 1) * 256 + d];
    ((float4*)out)[i] = make_float4(a.x + b.x, a.y + b.y, a.z + b.z, a.w + b.w);
}

// ---------------- launcher ----------------
extern "C" void kernel_launch(void* const* d_in, const int* in_sizes, int n_in,
                              void* d_out, int out_size) {
    const float* x  = (const float*)d_in[0];
    const float* nz = (const float*)d_in[1];
    const float* Wr = (const float*)d_in[2];
    const float* Wn = (const float*)d_in[3];
    const float* W1 = (const float*)d_in[4];
    const float* W2 = (const float*)d_in[5];
    float* out = (float*)d_out;

    constexpr int DS0 = NSTAGE * (2 * A_BYTES + 2 * B_BYTES);  // 215040
    constexpr int DS1 = NSTAGE * (A_BYTES + B_BYTES);          // 107520
    cudaFuncSetAttribute(moe_mma<0>, cudaFuncAttributeMaxDynamicSharedMemorySize, DS0);
    cudaFuncSetAttribute(moe_mma<1>, cudaFuncAttributeMaxDynamicSharedMemorySize, DS1);

    zero_meta_kernel<<<1, 32>>>();                                   // 1
    prep_kernel<<<PB_RT, 256>>>(x, nz, Wr, Wn, W1, W2);              // 2
    scanbuild_kernel<<<1, 1024>>>();                                 // 3
    // 4 (profiled): GEMM1  M=cnt N=4096 K=1024, 3 terms
    moe_mma<0><<<dim3(NTOK / 128, HDIM / 128, NEXP), 256, DS0>>>();
    // 5: GEMM2  M=cnt N=1024 K=4096, 1 term
    moe_mma<1><<<dim3(DDIM / 128, NTOK / 128, NEXP), 256, DS1>>>();
    combine_kernel<<<(NTOK * DDIM / 4) / 256, 256>>>(out);           // 6
}

// round 7
// speedup vs baseline: 1.8403x; 1.0959x over previous
#include <cuda_runtime.h>
#include <cuda_fp16.h>
#include <math.h>
#include <stdint.h>

#define NTOK 8192
#define DDIM 1024
#define HDIM 4096
#define NEXP 8
#define NPAIR (NTOK * 2)

// ---------------- scratch (device globals: allocation-free rule) ----------------
__device__ __half gXh[(size_t)NTOK * DDIM];   // fp16 hi of x (token order)
__device__ __half gXl[(size_t)NTOK * DDIM];   // fp16 residual of x
__device__ __half gH[(size_t)NPAIR * HDIM];   // h = relu(u)^2, fp16, grouped
__device__ __half gW1h[(size_t)NEXP * DDIM * HDIM];
__device__ __half gW1l[(size_t)NEXP * DDIM * HDIM];
__device__ __half gW2h[(size_t)NEXP * HDIM * DDIM];
__device__ float g_ys[(size_t)NPAIR * DDIM];
__device__ int   g_tl[NPAIR];
__device__ float g_gl[NPAIR];
__device__ int   g_counts[NEXP];
__device__ int   g_offsets[NEXP + 1];
__device__ int   g_cursor[NEXP];
__device__ int   g_tok_e[NTOK];
__device__ float g_tok_g[NTOK * 2];

// ---------------- helpers ----------------
__device__ __forceinline__ uint32_t hpack2(float a, float b) {
    __half2 h = __floats2half2_rn(a, b);
    return *(uint32_t*)&h;
}
__device__ __forceinline__ uint32_t lpack2(float a, float b) {
    float ra = a - __half2float(__float2half_rn(a));
    float rb = b - __half2float(__float2half_rn(b));
    __half2 h = __floats2half2_rn(ra, rb);
    return *(uint32_t*)&h;
}

// ---------------- launch 1: zero meta ----------------
__global__ void zero_meta_kernel() {
    int i = threadIdx.x;
    if (i < NEXP) { g_counts[i] = 0; g_cursor[i] = 0; }
}

// ---------------- launch 2: fused prep (splitW1 | W2 hi | splitX | route) ----
#define PB_W1 32768
#define PB_W2 65536
#define PB_X  73728
#define PB_RT 74752

__global__ __launch_bounds__(256)
void prep_kernel(const float* __restrict__ x, const float* __restrict__ noisep,
                 const float* __restrict__ Wr, const float* __restrict__ Wn,
                 const float* __restrict__ W1, const float* __restrict__ W2) {
    int b = blockIdx.x, tid = threadIdx.x;
    if (b < PB_W1) {
        size_t i = ((size_t)b * 256 + tid);
        float4 v = ((const float4*)W1)[i];
        *(uint2*)(gW1h + i * 4) = make_uint2(hpack2(v.x, v.y), hpack2(v.z, v.w));
        *(uint2*)(gW1l + i * 4) = make_uint2(lpack2(v.x, v.y), lpack2(v.z, v.w));
    } else if (b < PB_W2) {
        size_t i = ((size_t)(b - PB_W1) * 256 + tid);
        float4 v = ((const float4*)W2)[i];
        *(uint2*)(gW2h + i * 4) = make_uint2(hpack2(v.x, v.y), hpack2(v.z, v.w));
    } else if (b < PB_X) {
        int t = b - PB_W2;
        float4 v = ((const float4*)(x + (size_t)t * DDIM))[tid];
        size_t o = (size_t)t * DDIM + tid * 4;
        *(uint2*)(gXh + o) = make_uint2(hpack2(v.x, v.y), hpack2(v.z, v.w));
        *(uint2*)(gXl + o) = make_uint2(lpack2(v.x, v.y), lpack2(v.z, v.w));
    } else {
        // router: one warp per token
        int warp = tid >> 5, lane = tid & 31;
        int t = (b - PB_X) * 8 + warp;
        const float* xr = x + (size_t)t * DDIM;
        float xs[32];
#pragma unroll
        for (int i = 0; i < 32; i++) xs[i] = xr[lane + 32 * i];
        float nz[NEXP];
#pragma unroll
        for (int e = 0; e < NEXP; e++) {
            const float* wr = Wr + e * DDIM;
            const float* wn = Wn + e * DDIM;
            float a = 0.f, bb = 0.f;
#pragma unroll
            for (int i = 0; i < 32; i++) {
                float xv = xs[i];
                a  = fmaf(xv, wr[lane + 32 * i], a);
                bb = fmaf(xv, wn[lane + 32 * i], bb);
            }
#pragma unroll
            for (int o = 16; o > 0; o >>= 1) {
                a  += __shfl_xor_sync(0xffffffffu, a, o);
                bb += __shfl_xor_sync(0xffffffffu, bb, o);
            }
            float sp = fmaxf(bb, 0.f) + log1pf(expf(-fabsf(bb)));
            nz[e] = a + noisep[t * NEXP + e] * sp;
        }
        if (lane == 0) {
            int e0 = 0; float v0 = nz[0];
#pragma unroll
            for (int e = 1; e < NEXP; e++) if (nz[e] > v0) { v0 = nz[e]; e0 = e; }
            int e1 = (e0 == 0) ? 1 : 0; float v1 = nz[e1];
#pragma unroll
            for (int e = 0; e < NEXP; e++)
                if (e != e0 && nz[e] > v1) { v1 = nz[e]; e1 = e; }
            float m  = fmaxf(v0, v1);
            float z0 = expf(v0 - m), z1 = expf(v1 - m);
            float inv = 1.f / (z0 + z1);
            g_tok_e[t] = e0 | (e1 << 8);
            g_tok_g[t * 2 + 0] = z0 * inv;
            g_tok_g[t * 2 + 1] = z1 * inv;
            atomicAdd(&g_counts[e0], 1);
            atomicAdd(&g_counts[e1], 1);
        }
    }
}

// ---------------- launch 3: scan + build (single CTA) ----------------
__global__ void scanbuild_kernel() {
    int tid = threadIdx.x;
    if (tid == 0) {
        int s = 0;
        for (int e = 0; e < NEXP; e++) { g_offsets[e] = s; s += g_counts[e]; }
        g_offsets[NEXP] = s;
    }
    __syncthreads();
    for (int t = tid; t < NTOK; t += 1024) {
        int ee = g_tok_e[t];
        int e0 = ee & 0xff, e1 = ee >> 8;
        int s  = atomicAdd(&g_cursor[e0], 1);
        int i0 = g_offsets[e0] + s;
        g_tl[i0] = t * 2;     g_gl[i0] = g_tok_g[t * 2];
        s = atomicAdd(&g_cursor[e1], 1);
        int i1 = g_offsets[e1] + s;
        g_tl[i1] = t * 2 + 1; g_gl[i1] = g_tok_g[t * 2 + 1];
    }
}

// ---------------- mma helpers ----------------
__device__ __forceinline__ void ldsm4(uint32_t (&r)[4], uint32_t a) {
    asm volatile("ldmatrix.sync.aligned.m8n8.x4.shared.b16 {%0,%1,%2,%3}, [%4];\n"
                 : "=r"(r[0]), "=r"(r[1]), "=r"(r[2]), "=r"(r[3]) : "r"(a));
}
__device__ __forceinline__ void ldsm4t(uint32_t (&r)[4], uint32_t a) {
    asm volatile("ldmatrix.sync.aligned.m8n8.x4.trans.shared.b16 {%0,%1,%2,%3}, [%4];\n"
                 : "=r"(r[0]), "=r"(r[1]), "=r"(r[2]), "=r"(r[3]) : "r"(a));
}
__device__ __forceinline__ void mma16816(float (&c)[4], const uint32_t (&a)[4],
                                         uint32_t b0, uint32_t b1) {
    asm volatile(
        "mma.sync.aligned.m16n8k16.row.col.f32.f16.f16.f32 "
        "{%0,%1,%2,%3},{%4,%5,%6,%7},{%8,%9},{%0,%1,%2,%3};\n"
        : "+f"(c[0]), "+f"(c[1]), "+f"(c[2]), "+f"(c[3])
        : "r"(a[0]), "r"(a[1]), "r"(a[2]), "r"(a[3]), "r"(b0), "r"(b1));
}
__device__ __forceinline__ void cpa16(uint32_t d, const void* s) {
    asm volatile("cp.async.cg.shared.global [%0], [%1], 16;" :: "r"(d), "l"(s)
                 : "memory");
}
__device__ __forceinline__ void cpa_commit() {
    asm volatile("cp.async.commit_group;" ::: "memory");
}
__device__ __forceinline__ void cpa_wait1() {
    asm volatile("cp.async.wait_group 1;" ::: "memory");
}

// smem geometry: CTA tile 128(M) x 256(N), BK=64.
// A: 128 rows x 144B pitch (128B data + 16 pad)  -> conflict-free ldmatrix
// B: 64 k-rows x 544B pitch (512B data + 32 pad) -> conflict-free ldmatrix.trans
#define A_BYTES 18432
#define B_BYTES 34816

// ---------------- grouped split-fp16 mma.sync GEMM ----------------
// MODE 0: h = relu(x @ W1[e])^2 -> gH (fp16)   K=1024 N=4096, 3 terms, 2 stages
// MODE 1: ys = gate * (h @ W2[e]) -> g_ys      K=4096 N=1024, 1 term,  3 stages
template <int MODE>
__global__ __launch_bounds__(256, 1)
void moe_mma() {
    constexpr int K      = (MODE == 0) ? DDIM : HDIM;
    constexpr int NGL    = (MODE == 0) ? HDIM : DDIM;
    constexpr int NC     = K / 64;
    constexpr int NSTAGE = (MODE == 0) ? 2 : 3;
    constexpr int OFF_AL = A_BYTES;                          // mode0 only
    constexpr int OFF_BH = (MODE == 0) ? 2 * A_BYTES : A_BYTES;
    constexpr int OFF_BL = OFF_BH + B_BYTES;                 // mode0 only
    constexpr int STG    = (MODE == 0) ? OFF_BL + B_BYTES : OFF_BH + B_BYTES;

    const int e   = blockIdx.z;
    const int cnt = g_counts[e];
    const int mT  = (MODE == 0) ? blockIdx.x : blockIdx.y;
    if (mT * 128 >= cnt) return;
    const int nT  = (MODE == 0) ? blockIdx.y : blockIdx.x;
    const int off = g_offsets[e];
    const int nb  = nT * 256;

    extern __shared__ char dsm[];
    const uint32_t ab = (uint32_t)__cvta_generic_to_shared(dsm);

    const int tid = threadIdx.x;
    const int warp = tid >> 5, lane = tid & 31;

    const __half* Ah = (MODE == 0) ? gXh : gH;
    const __half* Al = gXl;                                  // mode0 only
    const __half* Bh = ((MODE == 0) ? gW1h : gW2h) + (size_t)e * DDIM * HDIM;
    const __half* Bl = gW1l + (size_t)e * DDIM * HDIM;       // mode0 only

    // ---- cp.async slots: A 4 rows x 16B/thread, B 8 rows x 16B/thread ----
    const int aC = tid & 7;            // 16B chunk in 128B row
    const int aR = tid >> 3;           // 0..31
    uint32_t aSrc[4]; uint32_t aDst[4];
#pragma unroll
    for (int i = 0; i < 4; i++) {
        int r  = aR + i * 32;
        int rm = min(mT * 128 + r, cnt - 1);
        uint32_t rowbase;
        if (MODE == 0) rowbase = (uint32_t)(g_tl[off + rm] >> 1) * DDIM;
        else           rowbase = (uint32_t)(off + rm) * HDIM;
        aSrc[i] = rowbase + aC * 8;
        aDst[i] = (uint32_t)(r * 144 + aC * 16);
    }
    const int bC = tid & 31;           // 16B chunk in 512B row
    const int bR = tid >> 5;           // 0..7
    uint32_t bSrc[8]; uint32_t bDst[8];
#pragma unroll
    for (int i = 0; i < 8; i++) {
        int r = bR + i * 8;
        bSrc[i] = (uint32_t)(r * NGL + nb + bC * 8);
        bDst[i] = (uint32_t)(r * 544 + bC * 16);
    }

    auto ldc = [&](int c) {
        uint32_t sb = ab + (uint32_t)(c % NSTAGE) * STG;
        uint32_t k0 = c * 64;
#pragma unroll
        for (int i = 0; i < 4; i++) {
            cpa16(sb + aDst[i], Ah + aSrc[i] + k0);
            if (MODE == 0) cpa16(sb + OFF_AL + aDst[i], Al + aSrc[i] + k0);
        }
        uint32_t bk = k0 * NGL;
#pragma unroll
        for (int i = 0; i < 8; i++) {
            cpa16(sb + OFF_BH + bDst[i], Bh + bSrc[i] + bk);
            if (MODE == 0) cpa16(sb + OFF_BL + bDst[i], Bl + bSrc[i] + bk);
        }
        cpa_commit();
    };

    // warp grid: 2 (M) x 4 (N) -> 64x64 warp tile
    const int wm = (warp >> 2) * 64;
    const int wn = (warp & 3) * 64;

    float acc[4][8][4];
#pragma unroll
    for (int a = 0; a < 4; a++)
#pragma unroll
        for (int b = 0; b < 8; b++)
#pragma unroll
            for (int c = 0; c < 4; c++) acc[a][b][c] = 0.f;

    const int aRow  = lane & 15;
    const int aCol  = (lane >> 4) << 3;
    const int bRowL = ((lane >> 3) & 1) * 8 + (lane & 7);
    const int bColL = (lane >> 4) * 8;

    auto compute = [&](int c) {
        uint32_t sb = ab + (uint32_t)(c % NSTAGE) * STG;
#pragma unroll
        for (int ks = 0; ks < 4; ks++) {
            uint32_t afh[4][4];
#pragma unroll
            for (int ms = 0; ms < 4; ms++)
                ldsm4(afh[ms], sb + (uint32_t)((wm + ms * 16 + aRow) * 144 +
                                               (ks * 16 + aCol) * 2));
            uint32_t afl[4][4];
            if (MODE == 0) {
#pragma unroll
                for (int ms = 0; ms < 4; ms++)
                    ldsm4(afl[ms], sb + OFF_AL +
                          (uint32_t)((wm + ms * 16 + aRow) * 144 +
                                     (ks * 16 + aCol) * 2));
            }
#pragma unroll
            for (int g = 0; g < 4; g++) {
                uint32_t brow = (uint32_t)((ks * 16 + bRowL) * 544 +
                                           (wn + g * 16 + bColL) * 2);
                uint32_t qh[4];
                ldsm4t(qh, sb + OFF_BH + brow);
                // hi*hi: 8 independent accumulators back-to-back
#pragma unroll
                for (int ms = 0; ms < 4; ms++) {
                    mma16816(acc[ms][g * 2 + 0], afh[ms], qh[0], qh[1]);
                    mma16816(acc[ms][g * 2 + 1], afh[ms], qh[2], qh[3]);
                }
                if (MODE == 0) {
                    uint32_t ql[4];
                    ldsm4t(ql, sb + OFF_BL + brow);
#pragma unroll
                    for (int ms = 0; ms < 4; ms++) {     // hi*lo
                        mma16816(acc[ms][g * 2 + 0], afh[ms], ql[0], ql[1]);
                        mma16816(acc[ms][g * 2 + 1], afh[ms], ql[2], ql[3]);
                    }
#pragma unroll
                    for (int ms = 0; ms < 4; ms++) {     // lo*hi
                        mma16816(acc[ms][g * 2 + 0], afl[ms], qh[0], qh[1]);
                        mma16816(acc[ms][g * 2 + 1], afl[ms], qh[2], qh[3]);
                    }
                }
            }
        }
    };

    if (MODE == 0) {
        // 2-stage pipeline, 2 barriers per chunk
        ldc(0);
        for (int c = 0; c < NC; c++) {
            if (c + 1 < NC) ldc(c + 1); else cpa_commit();
            cpa_wait1();
            __syncthreads();
            compute(c);
            __syncthreads();
        }
    } else {
        // 3-stage pipeline, 1 barrier per chunk
        ldc(0);
        ldc(1);
        for (int c = 0; c < NC; c++) {
            cpa_wait1();
            __syncthreads();
            if (c + 2 < NC) ldc(c + 2); else cpa_commit();
            compute(c);
        }
    }

    // ---------------- epilogue ----------------
#pragma unroll
    for (int ms = 0; ms < 4; ms++) {
        int r0 = wm + ms * 16 + (lane >> 2);
#pragma unroll
        for (int half = 0; half < 2; half++) {
            int r  = r0 + half * 8;
            int gm = mT * 128 + r;
            if (gm < cnt) {
                int idx = off + gm;
                if (MODE == 0) {
                    __half* oh = gH + (size_t)idx * HDIM + nb;
#pragma unroll
                    for (int ns = 0; ns < 8; ns++) {
                        int cc  = wn + ns * 8 + (lane & 3) * 2;
                        float v0 = fmaxf(acc[ms][ns][half * 2 + 0], 0.f);
                        float v1 = fmaxf(acc[ms][ns][half * 2 + 1], 0.f);
                        v0 *= v0; v1 *= v1;
                        *(uint32_t*)(oh + cc) = hpack2(v0, v1);
                    }
                } else {
                    int   pr = g_tl[idx];
                    float gt = g_gl[idx];
                    float* yo = g_ys + (size_t)pr * DDIM + nb;
#pragma unroll
                    for (int ns = 0; ns < 8; ns++) {
                        int cc = wn + ns * 8 + (lane & 3) * 2;
                        *(float2*)(yo + cc) =
                            make_float2(acc[ms][ns][half * 2 + 0] * gt,
                                        acc[ms][ns][half * 2 + 1] * gt);
                    }
                }
            }
        }
    }
}

__global__ void combine_kernel(float* __restrict__ out) {
    size_t i = (size_t)blockIdx.x * blockDim.x + threadIdx.x;  // float4 idx
    const float4* ys = (const float4*)g_ys;
    size_t t = i >> 8;
    size_t d = i & 255;
    float4 a = ys[(t * 2 + 0) * 256 + d];
    float4 b = ys[(t * 2 + 1) * 256 + d];
    ((float4*)out)[i] = make_float4(a.x + b.x, a.y + b.y, a.z + b.z, a.w + b.w);
}

// ---------------- launcher ----------------
extern "C" void kernel_launch(void* const* d_in, const int* in_sizes, int n_in,
                              void* d_out, int out_size) {
    const float* x  = (const float*)d_in[0];
    const float* nz = (const float*)d_in[1];
    const float* Wr = (const float*)d_in[2];
    const float* Wn = (const float*)d_in[3];
    const float* W1 = (const float*)d_in[4];
    const float* W2 = (const float*)d_in[5];
    float* out = (float*)d_out;

    constexpr int DS0 = 2 * (2 * A_BYTES + 2 * B_BYTES);  // 212992
    constexpr int DS1 = 3 * (A_BYTES + B_BYTES);          // 159744
    cudaFuncSetAttribute(moe_mma<0>, cudaFuncAttributeMaxDynamicSharedMemorySize, DS0);
    cudaFuncSetAttribute(moe_mma<1>, cudaFuncAttributeMaxDynamicSharedMemorySize, DS1);

    zero_meta_kernel<<<1, 32>>>();                                   // 1
    prep_kernel<<<PB_RT, 256>>>(x, nz, Wr, Wn, W1, W2);              // 2
    scanbuild_kernel<<<1, 1024>>>();                                 // 3
    // 4 (profiled): GEMM1  M=cnt N=4096 K=1024, 3 terms
    moe_mma<0><<<dim3(NTOK / 128, HDIM / 256, NEXP), 256, DS0>>>();
    // 5: GEMM2  M=cnt N=1024 K=4096, 1 term
    moe_mma<1><<<dim3(DDIM / 256, NTOK / 128, NEXP), 256, DS1>>>();
    combine_kernel<<<(NTOK * DDIM / 4) / 256, 256>>>(out);           // 6
}

// round 8
// speedup vs baseline: 2.2447x; 1.2198x over previous
#include <cuda_runtime.h>
#include <cuda_fp16.h>
#include <math.h>
#include <stdint.h>

#define NTOK 8192
#define DDIM 1024
#define HDIM 4096
#define NEXP 8
#define NPAIR (NTOK * 2)

// ---------------- scratch (device globals: allocation-free rule) ----------------
__device__ __half gXh[(size_t)NTOK * DDIM];   // fp16 x (token order)
__device__ __half gH[(size_t)NPAIR * HDIM];   // h = relu(u)^2, fp16, grouped
__device__ __half gW1h[(size_t)NEXP * DDIM * HDIM];
__device__ __half gW1l[(size_t)NEXP * DDIM * HDIM];
__device__ __half gW2h[(size_t)NEXP * HDIM * DDIM];
__device__ float g_ys[(size_t)NPAIR * DDIM];
__device__ int   g_tl[NPAIR];
__device__ float g_gl[NPAIR];
__device__ int   g_counts[NEXP];
__device__ int   g_offsets[NEXP + 1];
__device__ int   g_cursor[NEXP];
__device__ int   g_tok_e[NTOK];
__device__ float g_tok_g[NTOK * 2];

// ---------------- helpers ----------------
__device__ __forceinline__ uint32_t hpack2(float a, float b) {
    __half2 h = __floats2half2_rn(a, b);
    return *(uint32_t*)&h;
}
__device__ __forceinline__ uint32_t lpack2(float a, float b) {
    float ra = a - __half2float(__float2half_rn(a));
    float rb = b - __half2float(__float2half_rn(b));
    __half2 h = __floats2half2_rn(ra, rb);
    return *(uint32_t*)&h;
}

// ---------------- launch 1: zero meta ----------------
__global__ void zero_meta_kernel() {
    int i = threadIdx.x;
    if (i < NEXP) { g_counts[i] = 0; g_cursor[i] = 0; }
}

// ---------------- launch 2: fused prep (splitW1 | W2 hi | X hi | route) ----
#define PB_W1 32768
#define PB_W2 65536
#define PB_X  73728
#define PB_RT 74752

__global__ __launch_bounds__(256)
void prep_kernel(const float* __restrict__ x, const float* __restrict__ noisep,
                 const float* __restrict__ Wr, const float* __restrict__ Wn,
                 const float* __restrict__ W1, const float* __restrict__ W2) {
    int b = blockIdx.x, tid = threadIdx.x;
    if (b < PB_W1) {
        size_t i = ((size_t)b * 256 + tid);
        float4 v = ((const float4*)W1)[i];
        *(uint2*)(gW1h + i * 4) = make_uint2(hpack2(v.x, v.y), hpack2(v.z, v.w));
        *(uint2*)(gW1l + i * 4) = make_uint2(lpack2(v.x, v.y), lpack2(v.z, v.w));
    } else if (b < PB_W2) {
        size_t i = ((size_t)(b - PB_W1) * 256 + tid);
        float4 v = ((const float4*)W2)[i];
        *(uint2*)(gW2h + i * 4) = make_uint2(hpack2(v.x, v.y), hpack2(v.z, v.w));
    } else if (b < PB_X) {
        int t = b - PB_W2;
        float4 v = ((const float4*)(x + (size_t)t * DDIM))[tid];
        size_t o = (size_t)t * DDIM + tid * 4;
        *(uint2*)(gXh + o) = make_uint2(hpack2(v.x, v.y), hpack2(v.z, v.w));
    } else {
        // router: one warp per token
        int warp = tid >> 5, lane = tid & 31;
        int t = (b - PB_X) * 8 + warp;
        const float* xr = x + (size_t)t * DDIM;
        float xs[32];
#pragma unroll
        for (int i = 0; i < 32; i++) xs[i] = xr[lane + 32 * i];
        float nz[NEXP];
#pragma unroll
        for (int e = 0; e < NEXP; e++) {
            const float* wr = Wr + e * DDIM;
            const float* wn = Wn + e * DDIM;
            float a = 0.f, bb = 0.f;
#pragma unroll
            for (int i = 0; i < 32; i++) {
                float xv = xs[i];
                a  = fmaf(xv, wr[lane + 32 * i], a);
                bb = fmaf(xv, wn[lane + 32 * i], bb);
            }
#pragma unroll
            for (int o = 16; o > 0; o >>= 1) {
                a  += __shfl_xor_sync(0xffffffffu, a, o);
                bb += __shfl_xor_sync(0xffffffffu, bb, o);
            }
            float sp = fmaxf(bb, 0.f) + log1pf(expf(-fabsf(bb)));
            nz[e] = a + noisep[t * NEXP + e] * sp;
        }
        if (lane == 0) {
            int e0 = 0; float v0 = nz[0];
#pragma unroll
            for (int e = 1; e < NEXP; e++) if (nz[e] > v0) { v0 = nz[e]; e0 = e; }
            int e1 = (e0 == 0) ? 1 : 0; float v1 = nz[e1];
#pragma unroll
            for (int e = 0; e < NEXP; e++)
                if (e != e0 && nz[e] > v1) { v1 = nz[e]; e1 = e; }
            float m  = fmaxf(v0, v1);
            float z0 = expf(v0 - m), z1 = expf(v1 - m);
            float inv = 1.f / (z0 + z1);
            g_tok_e[t] = e0 | (e1 << 8);
            g_tok_g[t * 2 + 0] = z0 * inv;
            g_tok_g[t * 2 + 1] = z1 * inv;
            atomicAdd(&g_counts[e0], 1);
            atomicAdd(&g_counts[e1], 1);
        }
    }
}

// ---------------- launch 3: scan + build (single CTA) ----------------
__global__ void scanbuild_kernel() {
    int tid = threadIdx.x;
    if (tid == 0) {
        int s = 0;
        for (int e = 0; e < NEXP; e++) { g_offsets[e] = s; s += g_counts[e]; }
        g_offsets[NEXP] = s;
    }
    __syncthreads();
    for (int t = tid; t < NTOK; t += 1024) {
        int ee = g_tok_e[t];
        int e0 = ee & 0xff, e1 = ee >> 8;
        int s  = atomicAdd(&g_cursor[e0], 1);
        int i0 = g_offsets[e0] + s;
        g_tl[i0] = t * 2;     g_gl[i0] = g_tok_g[t * 2];
        s = atomicAdd(&g_cursor[e1], 1);
        int i1 = g_offsets[e1] + s;
        g_tl[i1] = t * 2 + 1; g_gl[i1] = g_tok_g[t * 2 + 1];
    }
}

// ---------------- mma helpers ----------------
__device__ __forceinline__ void ldsm4(uint32_t (&r)[4], uint32_t a) {
    asm volatile("ldmatrix.sync.aligned.m8n8.x4.shared.b16 {%0,%1,%2,%3}, [%4];\n"
                 : "=r"(r[0]), "=r"(r[1]), "=r"(r[2]), "=r"(r[3]) : "r"(a));
}
__device__ __forceinline__ void ldsm4t(uint32_t (&r)[4], uint32_t a) {
    asm volatile("ldmatrix.sync.aligned.m8n8.x4.trans.shared.b16 {%0,%1,%2,%3}, [%4];\n"
                 : "=r"(r[0]), "=r"(r[1]), "=r"(r[2]), "=r"(r[3]) : "r"(a));
}
__device__ __forceinline__ void mma16816(float (&c)[4], const uint32_t (&a)[4],
                                         uint32_t b0, uint32_t b1) {
    asm volatile(
        "mma.sync.aligned.m16n8k16.row.col.f32.f16.f16.f32 "
        "{%0,%1,%2,%3},{%4,%5,%6,%7},{%8,%9},{%0,%1,%2,%3};\n"
        : "+f"(c[0]), "+f"(c[1]), "+f"(c[2]), "+f"(c[3])
        : "r"(a[0]), "r"(a[1]), "r"(a[2]), "r"(a[3]), "r"(b0), "r"(b1));
}
__device__ __forceinline__ void cpa16(uint32_t d, const void* s) {
    asm volatile("cp.async.cg.shared.global [%0], [%1], 16;" :: "r"(d), "l"(s)
                 : "memory");
}
__device__ __forceinline__ void cpa_commit() {
    asm volatile("cp.async.commit_group;" ::: "memory");
}
__device__ __forceinline__ void cpa_wait1() {
    asm volatile("cp.async.wait_group 1;" ::: "memory");
}

// smem geometry: CTA tile 128(M) x 256(N), BK=64.
// A: 128 rows x 144B pitch (128B data + 16 pad)  -> conflict-free ldmatrix
// B: 64 k-rows x 544B pitch (512B data + 32 pad) -> conflict-free ldmatrix.trans
#define A_BYTES 18432
#define B_BYTES 34816

// ---------------- grouped split-fp16 mma.sync GEMM ----------------
// MODE 0: h = relu(x @ (W1h+W1l))^2 -> gH (fp16)  K=1024 N=4096, 2 terms, 2 stages
// MODE 1: ys = gate * (h @ W2h) -> g_ys           K=4096 N=1024, 1 term,  3 stages
template <int MODE>
__global__ __launch_bounds__(256, 1)
void moe_mma() {
    constexpr int K      = (MODE == 0) ? DDIM : HDIM;
    constexpr int NGL    = (MODE == 0) ? HDIM : DDIM;
    constexpr int NC     = K / 64;
    constexpr int NSTAGE = (MODE == 0) ? 2 : 3;
    constexpr int OFF_BH = A_BYTES;
    constexpr int OFF_BL = OFF_BH + B_BYTES;                 // mode0 only
    constexpr int STG    = (MODE == 0) ? OFF_BL + B_BYTES : OFF_BH + B_BYTES;

    const int e   = blockIdx.z;
    const int cnt = g_counts[e];
    const int mT  = (MODE == 0) ? blockIdx.x : blockIdx.y;
    if (mT * 128 >= cnt) return;
    const int nT  = (MODE == 0) ? blockIdx.y : blockIdx.x;
    const int off = g_offsets[e];
    const int nb  = nT * 256;

    extern __shared__ char dsm[];
    const uint32_t ab = (uint32_t)__cvta_generic_to_shared(dsm);

    const int tid = threadIdx.x;
    const int warp = tid >> 5, lane = tid & 31;

    const __half* Ah = (MODE == 0) ? gXh : gH;
    const __half* Bh = ((MODE == 0) ? gW1h : gW2h) + (size_t)e * DDIM * HDIM;
    const __half* Bl = gW1l + (size_t)e * DDIM * HDIM;       // mode0 only

    // ---- cp.async slots: A 4 rows x 16B/thread, B 8 rows x 16B/thread ----
    const int aC = tid & 7;            // 16B chunk in 128B row
    const int aR = tid >> 3;           // 0..31
    uint32_t aSrc[4]; uint32_t aDst[4];
#pragma unroll
    for (int i = 0; i < 4; i++) {
        int r  = aR + i * 32;
        int rm = min(mT * 128 + r, cnt - 1);
        uint32_t rowbase;
        if (MODE == 0) rowbase = (uint32_t)(g_tl[off + rm] >> 1) * DDIM;
        else           rowbase = (uint32_t)(off + rm) * HDIM;
        aSrc[i] = rowbase + aC * 8;
        aDst[i] = (uint32_t)(r * 144 + aC * 16);
    }
    const int bC = tid & 31;           // 16B chunk in 512B row
    const int bR = tid >> 5;           // 0..7
    uint32_t bSrc[8]; uint32_t bDst[8];
#pragma unroll
    for (int i = 0; i < 8; i++) {
        int r = bR + i * 8;
        bSrc[i] = (uint32_t)(r * NGL + nb + bC * 8);
        bDst[i] = (uint32_t)(r * 544 + bC * 16);
    }

    auto ldc = [&](int c) {
        uint32_t sb = ab + (uint32_t)(c % NSTAGE) * STG;
        uint32_t k0 = c * 64;
#pragma unroll
        for (int i = 0; i < 4; i++)
            cpa16(sb + aDst[i], Ah + aSrc[i] + k0);
        uint32_t bk = k0 * NGL;
#pragma unroll
        for (int i = 0; i < 8; i++) {
            cpa16(sb + OFF_BH + bDst[i], Bh + bSrc[i] + bk);
            if (MODE == 0) cpa16(sb + OFF_BL + bDst[i], Bl + bSrc[i] + bk);
        }
        cpa_commit();
    };

    // warp grid: 2 (M) x 4 (N) -> 64x64 warp tile
    const int wm = (warp >> 2) * 64;
    const int wn = (warp & 3) * 64;

    float acc[4][8][4];
#pragma unroll
    for (int a = 0; a < 4; a++)
#pragma unroll
        for (int b = 0; b < 8; b++)
#pragma unroll
            for (int c = 0; c < 4; c++) acc[a][b][c] = 0.f;

    const int aRow  = lane & 15;
    const int aCol  = (lane >> 4) << 3;
    const int bRowL = ((lane >> 3) & 1) * 8 + (lane & 7);
    const int bColL = (lane >> 4) * 8;

    auto compute = [&](int c) {
        uint32_t sb = ab + (uint32_t)(c % NSTAGE) * STG;
#pragma unroll
        for (int ks = 0; ks < 4; ks++) {
            uint32_t afh[4][4];
#pragma unroll
            for (int ms = 0; ms < 4; ms++)
                ldsm4(afh[ms], sb + (uint32_t)((wm + ms * 16 + aRow) * 144 +
                                               (ks * 16 + aCol) * 2));
#pragma unroll
            for (int g = 0; g < 4; g++) {
                uint32_t brow = (uint32_t)((ks * 16 + bRowL) * 544 +
                                           (wn + g * 16 + bColL) * 2);
                uint32_t qh[4];
                ldsm4t(qh, sb + OFF_BH + brow);
                // hi*hi: 8 independent accumulators back-to-back
#pragma unroll
                for (int ms = 0; ms < 4; ms++) {
                    mma16816(acc[ms][g * 2 + 0], afh[ms], qh[0], qh[1]);
                    mma16816(acc[ms][g * 2 + 1], afh[ms], qh[2], qh[3]);
                }
                if (MODE == 0) {
                    uint32_t ql[4];
                    ldsm4t(ql, sb + OFF_BL + brow);
#pragma unroll
                    for (int ms = 0; ms < 4; ms++) {     // hi*lo
                        mma16816(acc[ms][g * 2 + 0], afh[ms], ql[0], ql[1]);
                        mma16816(acc[ms][g * 2 + 1], afh[ms], ql[2], ql[3]);
                    }
                }
            }
        }
    };

    if (MODE == 0) {
        // 2-stage pipeline, 2 barriers per chunk
        ldc(0);
        for (int c = 0; c < NC; c++) {
            if (c + 1 < NC) ldc(c + 1); else cpa_commit();
            cpa_wait1();
            __syncthreads();
            compute(c);
            __syncthreads();
        }
    } else {
        // 3-stage pipeline, 1 barrier per chunk
        ldc(0);
        ldc(1);
        for (int c = 0; c < NC; c++) {
            cpa_wait1();
            __syncthreads();
            if (c + 2 < NC) ldc(c + 2); else cpa_commit();
            compute(c);
        }
    }

    // ---------------- epilogue ----------------
#pragma unroll
    for (int ms = 0; ms < 4; ms++) {
        int r0 = wm + ms * 16 + (lane >> 2);
#pragma unroll
        for (int half = 0; half < 2; half++) {
            int r  = r0 + half * 8;
            int gm = mT * 128 + r;
            if (gm < cnt) {
                int idx = off + gm;
                if (MODE == 0) {
                    __half* oh = gH + (size_t)idx * HDIM + nb;
#pragma unroll
                    for (int ns = 0; ns < 8; ns++) {
                        int cc  = wn + ns * 8 + (lane & 3) * 2;
                        float v0 = fmaxf(acc[ms][ns][half * 2 + 0], 0.f);
                        float v1 = fmaxf(acc[ms][ns][half * 2 + 1], 0.f);
                        v0 *= v0; v1 *= v1;
                        *(uint32_t*)(oh + cc) = hpack2(v0, v1);
                    }
                } else {
                    int   pr = g_tl[idx];
                    float gt = g_gl[idx];
                    float* yo = g_ys + (size_t)pr * DDIM + nb;
#pragma unroll
                    for (int ns = 0; ns < 8; ns++) {
                        int cc = wn + ns * 8 + (lane & 3) * 2;
                        *(float2*)(yo + cc) =
                            make_float2(acc[ms][ns][half * 2 + 0] * gt,
                                        acc[ms][ns][half * 2 + 1] * gt);
                    }
                }
            }
        }
    }
}

__global__ void combine_kernel(float* __restrict__ out) {
    size_t i = (size_t)blockIdx.x * blockDim.x + threadIdx.x;  // float4 idx
    const float4* ys = (const float4*)g_ys;
    size_t t = i >> 8;
    size_t d = i & 255;
    float4 a = ys[(t * 2 + 0) * 256 + d];
    float4 b = ys[(t * 2 + 1) * 256 + d];
    ((float4*)out)[i] = make_float4(a.x + b.x, a.y + b.y, a.z + b.z, a.w + b.w);
}

// ---------------- launcher ----------------
extern "C" void kernel_launch(void* const* d_in, const int* in_sizes, int n_in,
                              void* d_out, int out_size) {
    const float* x  = (const float*)d_in[0];
    const float* nz = (const float*)d_in[1];
    const float* Wr = (const float*)d_in[2];
    const float* Wn = (const float*)d_in[3];
    const float* W1 = (const float*)d_in[4];
    const float* W2 = (const float*)d_in[5];
    float* out = (float*)d_out;

    constexpr int DS0 = 2 * (A_BYTES + 2 * B_BYTES);  // 176128
    constexpr int DS1 = 3 * (A_BYTES + B_BYTES);      // 159744
    cudaFuncSetAttribute(moe_mma<0>, cudaFuncAttributeMaxDynamicSharedMemorySize, DS0);
    cudaFuncSetAttribute(moe_mma<1>, cudaFuncAttributeMaxDynamicSharedMemorySize, DS1);

    zero_meta_kernel<<<1, 32>>>();                                   // 1
    prep_kernel<<<PB_RT, 256>>>(x, nz, Wr, Wn, W1, W2);              // 2
    scanbuild_kernel<<<1, 1024>>>();                                 // 3
    // 4 (profiled): GEMM1  M=cnt N=4096 K=1024, 2 terms
    moe_mma<0><<<dim3(NTOK / 128, HDIM / 256, NEXP), 256, DS0>>>();
    // 5: GEMM2  M=cnt N=1024 K=4096, 1 term
    moe_mma<1><<<dim3(DDIM / 256, NTOK / 128, NEXP), 256, DS1>>>();
    combine_kernel<<<(NTOK * DDIM / 4) / 256, 256>>>(out);           // 6
}

// round 9
// speedup vs baseline: 2.8626x; 1.2752x over previous
#include <cuda_runtime.h>
#include <cuda_fp16.h>
#include <math.h>
#include <stdint.h>

#define NTOK 8192
#define DDIM 1024
#define HDIM 4096
#define NEXP 8
#define NPAIR (NTOK * 2)

// ---------------- scratch (device globals: allocation-free rule) ----------------
__device__ __half gXh[(size_t)NTOK * DDIM];   // fp16 x (token order)
__device__ __half gH[(size_t)NPAIR * HDIM];   // h = relu(u)^2, fp16, grouped
__device__ __half gW1h[(size_t)NEXP * DDIM * HDIM];
__device__ __half gW2h[(size_t)NEXP * HDIM * DDIM];
__device__ float g_ys[(size_t)NPAIR * DDIM];
__device__ int   g_tl[NPAIR];
__device__ float g_gl[NPAIR];
__device__ int   g_counts[NEXP];
__device__ int   g_offsets[NEXP + 1];
__device__ int   g_cursor[NEXP];
__device__ int   g_tok_e[NTOK];
__device__ float g_tok_g[NTOK * 2];

// ---------------- helpers ----------------
__device__ __forceinline__ uint32_t hpack2(float a, float b) {
    __half2 h = __floats2half2_rn(a, b);
    return *(uint32_t*)&h;
}

// ---------------- launch 1: zero meta ----------------
__global__ void zero_meta_kernel() {
    int i = threadIdx.x;
    if (i < NEXP) { g_counts[i] = 0; g_cursor[i] = 0; }
}

// ---------------- launch 2: fused prep (W1 hi | W2 hi | X hi | route) ----
#define PB_W1 32768
#define PB_W2 65536
#define PB_X  73728
#define PB_RT 74752

__global__ __launch_bounds__(256)
void prep_kernel(const float* __restrict__ x, const float* __restrict__ noisep,
                 const float* __restrict__ Wr, const float* __restrict__ Wn,
                 const float* __restrict__ W1, const float* __restrict__ W2) {
    int b = blockIdx.x, tid = threadIdx.x;
    if (b < PB_W2) {
        const float* W = (b < PB_W1) ? W1 : W2;
        __half* oh = (b < PB_W1) ? gW1h : gW2h;
        size_t i = ((size_t)(b < PB_W1 ? b : b - PB_W1) * 256 + tid);
        float4 v = ((const float4*)W)[i];
        *(uint2*)(oh + i * 4) = make_uint2(hpack2(v.x, v.y), hpack2(v.z, v.w));
    } else if (b < PB_X) {
        int t = b - PB_W2;
        float4 v = ((const float4*)(x + (size_t)t * DDIM))[tid];
        size_t o = (size_t)t * DDIM + tid * 4;
        *(uint2*)(gXh + o) = make_uint2(hpack2(v.x, v.y), hpack2(v.z, v.w));
    } else {
        // router: one warp per token
        int warp = tid >> 5, lane = tid & 31;
        int t = (b - PB_X) * 8 + warp;
        const float* xr = x + (size_t)t * DDIM;
        float xs[32];
#pragma unroll
        for (int i = 0; i < 32; i++) xs[i] = xr[lane + 32 * i];
        float nz[NEXP];
#pragma unroll
        for (int e = 0; e < NEXP; e++) {
            const float* wr = Wr + e * DDIM;
            const float* wn = Wn + e * DDIM;
            float a = 0.f, bb = 0.f;
#pragma unroll
            for (int i = 0; i < 32; i++) {
                float xv = xs[i];
                a  = fmaf(xv, wr[lane + 32 * i], a);
                bb = fmaf(xv, wn[lane + 32 * i], bb);
            }
#pragma unroll
            for (int o = 16; o > 0; o >>= 1) {
                a  += __shfl_xor_sync(0xffffffffu, a, o);
                bb += __shfl_xor_sync(0xffffffffu, bb, o);
            }
            float sp = fmaxf(bb, 0.f) + log1pf(expf(-fabsf(bb)));
            nz[e] = a + noisep[t * NEXP + e] * sp;
        }
        if (lane == 0) {
            int e0 = 0; float v0 = nz[0];
#pragma unroll
            for (int e = 1; e < NEXP; e++) if (nz[e] > v0) { v0 = nz[e]; e0 = e; }
            int e1 = (e0 == 0) ? 1 : 0; float v1 = nz[e1];
#pragma unroll
            for (int e = 0; e < NEXP; e++)
                if (e != e0 && nz[e] > v1) { v1 = nz[e]; e1 = e; }
            float m  = fmaxf(v0, v1);
            float z0 = expf(v0 - m), z1 = expf(v1 - m);
            float inv = 1.f / (z0 + z1);
            g_tok_e[t] = e0 | (e1 << 8);
            g_tok_g[t * 2 + 0] = z0 * inv;
            g_tok_g[t * 2 + 1] = z1 * inv;
            atomicAdd(&g_counts[e0], 1);
            atomicAdd(&g_counts[e1], 1);
        }
    }
}

// ---------------- launch 3: scan + build (single CTA) ----------------
__global__ void scanbuild_kernel() {
    int tid = threadIdx.x;
    if (tid == 0) {
        int s = 0;
        for (int e = 0; e < NEXP; e++) { g_offsets[e] = s; s += g_counts[e]; }
        g_offsets[NEXP] = s;
    }
    __syncthreads();
    for (int t = tid; t < NTOK; t += 1024) {
        int ee = g_tok_e[t];
        int e0 = ee & 0xff, e1 = ee >> 8;
        int s  = atomicAdd(&g_cursor[e0], 1);
        int i0 = g_offsets[e0] + s;
        g_tl[i0] = t * 2;     g_gl[i0] = g_tok_g[t * 2];
        s = atomicAdd(&g_cursor[e1], 1);
        int i1 = g_offsets[e1] + s;
        g_tl[i1] = t * 2 + 1; g_gl[i1] = g_tok_g[t * 2 + 1];
    }
}

// ---------------- mma helpers ----------------
__device__ __forceinline__ void ldsm4(uint32_t (&r)[4], uint32_t a) {
    asm volatile("ldmatrix.sync.aligned.m8n8.x4.shared.b16 {%0,%1,%2,%3}, [%4];\n"
                 : "=r"(r[0]), "=r"(r[1]), "=r"(r[2]), "=r"(r[3]) : "r"(a));
}
__device__ __forceinline__ void ldsm4t(uint32_t (&r)[4], uint32_t a) {
    asm volatile("ldmatrix.sync.aligned.m8n8.x4.trans.shared.b16 {%0,%1,%2,%3}, [%4];\n"
                 : "=r"(r[0]), "=r"(r[1]), "=r"(r[2]), "=r"(r[3]) : "r"(a));
}
__device__ __forceinline__ void mma16816(float (&c)[4], const uint32_t (&a)[4],
                                         uint32_t b0, uint32_t b1) {
    asm volatile(
        "mma.sync.aligned.m16n8k16.row.col.f32.f16.f16.f32 "
        "{%0,%1,%2,%3},{%4,%5,%6,%7},{%8,%9},{%0,%1,%2,%3};\n"
        : "+f"(c[0]), "+f"(c[1]), "+f"(c[2]), "+f"(c[3])
        : "r"(a[0]), "r"(a[1]), "r"(a[2]), "r"(a[3]), "r"(b0), "r"(b1));
}
__device__ __forceinline__ void cpa16(uint32_t d, const void* s) {
    asm volatile("cp.async.cg.shared.global [%0], [%1], 16;" :: "r"(d), "l"(s)
                 : "memory");
}
__device__ __forceinline__ void cpa_commit() {
    asm volatile("cp.async.commit_group;" ::: "memory");
}
__device__ __forceinline__ void cpa_wait1() {
    asm volatile("cp.async.wait_group 1;" ::: "memory");
}

// smem geometry: CTA tile 128(M) x 256(N), BK=64.
// A: 128 rows x 144B pitch (128B data + 16 pad)  -> conflict-free ldmatrix
// B: 64 k-rows x 544B pitch (512B data + 32 pad) -> conflict-free ldmatrix.trans
#define A_BYTES 18432
#define B_BYTES 34816
#define STG     (A_BYTES + B_BYTES)
#define NSTAGE  3
#define DSMEM   (NSTAGE * STG)

// ---------------- grouped fp16 mma.sync GEMM (1 term both modes) ----------------
// MODE 0: h = relu(x @ W1h)^2 -> gH (fp16)   K=1024 N=4096
// MODE 1: ys = gate * (h @ W2h) -> g_ys      K=4096 N=1024
template <int MODE>
__global__ __launch_bounds__(256, 1)
void moe_mma() {
    constexpr int K   = (MODE == 0) ? DDIM : HDIM;
    constexpr int NGL = (MODE == 0) ? HDIM : DDIM;
    constexpr int NC  = K / 64;

    const int e   = blockIdx.z;
    const int cnt = g_counts[e];
    const int mT  = (MODE == 0) ? blockIdx.x : blockIdx.y;
    if (mT * 128 >= cnt) return;
    const int nT  = (MODE == 0) ? blockIdx.y : blockIdx.x;
    const int off = g_offsets[e];
    const int nb  = nT * 256;

    extern __shared__ char dsm[];
    const uint32_t ab = (uint32_t)__cvta_generic_to_shared(dsm);

    const int tid = threadIdx.x;
    const int warp = tid >> 5, lane = tid & 31;

    const __half* Ah = (MODE == 0) ? gXh : gH;
    const __half* Bh = ((MODE == 0) ? gW1h : gW2h) + (size_t)e * DDIM * HDIM;

    // ---- cp.async slots: A 4 rows x 16B/thread, B 8 rows x 16B/thread ----
    const int aC = tid & 7;            // 16B chunk in 128B row
    const int aR = tid >> 3;           // 0..31
    uint32_t aSrc[4]; uint32_t aDst[4];
#pragma unroll
    for (int i = 0; i < 4; i++) {
        int r  = aR + i * 32;
        int rm = min(mT * 128 + r, cnt - 1);
        uint32_t rowbase;
        if (MODE == 0) rowbase = (uint32_t)(g_tl[off + rm] >> 1) * DDIM;
        else           rowbase = (uint32_t)(off + rm) * HDIM;
        aSrc[i] = rowbase + aC * 8;
        aDst[i] = (uint32_t)(r * 144 + aC * 16);
    }
    const int bC = tid & 31;           // 16B chunk in 512B row
    const int bR = tid >> 5;           // 0..7
    uint32_t bSrc[8]; uint32_t bDst[8];
#pragma unroll
    for (int i = 0; i < 8; i++) {
        int r = bR + i * 8;
        bSrc[i] = (uint32_t)(r * NGL + nb + bC * 8);
        bDst[i] = (uint32_t)(r * 544 + bC * 16);
    }

    auto ldc = [&](int c) {
        uint32_t sb = ab + (uint32_t)(c % NSTAGE) * STG;
        uint32_t k0 = c * 64;
#pragma unroll
        for (int i = 0; i < 4; i++)
            cpa16(sb + aDst[i], Ah + aSrc[i] + k0);
        uint32_t bk = k0 * NGL;
#pragma unroll
        for (int i = 0; i < 8; i++)
            cpa16(sb + A_BYTES + bDst[i], Bh + bSrc[i] + bk);
        cpa_commit();
    };

    // warp grid: 2 (M) x 4 (N) -> 64x64 warp tile
    const int wm = (warp >> 2) * 64;
    const int wn = (warp & 3) * 64;

    float acc[4][8][4];
#pragma unroll
    for (int a = 0; a < 4; a++)
#pragma unroll
        for (int b = 0; b < 8; b++)
#pragma unroll
            for (int c = 0; c < 4; c++) acc[a][b][c] = 0.f;

    const int aRow  = lane & 15;
    const int aCol  = (lane >> 4) << 3;
    const int bRowL = ((lane >> 3) & 1) * 8 + (lane & 7);
    const int bColL = (lane >> 4) * 8;

    auto compute = [&](int c) {
        uint32_t sb = ab + (uint32_t)(c % NSTAGE) * STG;
#pragma unroll
        for (int ks = 0; ks < 4; ks++) {
            uint32_t afh[4][4];
#pragma unroll
            for (int ms = 0; ms < 4; ms++)
                ldsm4(afh[ms], sb + (uint32_t)((wm + ms * 16 + aRow) * 144 +
                                               (ks * 16 + aCol) * 2));
#pragma unroll
            for (int g = 0; g < 4; g++) {
                uint32_t brow = (uint32_t)((ks * 16 + bRowL) * 544 +
                                           (wn + g * 16 + bColL) * 2);
                uint32_t qh[4];
                ldsm4t(qh, sb + A_BYTES + brow);
                // 8 independent accumulators back-to-back
#pragma unroll
                for (int ms = 0; ms < 4; ms++) {
                    mma16816(acc[ms][g * 2 + 0], afh[ms], qh[0], qh[1]);
                    mma16816(acc[ms][g * 2 + 1], afh[ms], qh[2], qh[3]);
                }
            }
        }
    };

    // 3-stage pipeline, 1 barrier per chunk
    ldc(0);
    ldc(1);
    for (int c = 0; c < NC; c++) {
        cpa_wait1();
        __syncthreads();
        if (c + 2 < NC) ldc(c + 2); else cpa_commit();
        compute(c);
    }

    // ---------------- epilogue ----------------
#pragma unroll
    for (int ms = 0; ms < 4; ms++) {
        int r0 = wm + ms * 16 + (lane >> 2);
#pragma unroll
        for (int half = 0; half < 2; half++) {
            int r  = r0 + half * 8;
            int gm = mT * 128 + r;
            if (gm < cnt) {
                int idx = off + gm;
                if (MODE == 0) {
                    __half* oh = gH + (size_t)idx * HDIM + nb;
#pragma unroll
                    for (int ns = 0; ns < 8; ns++) {
                        int cc  = wn + ns * 8 + (lane & 3) * 2;
                        float v0 = fmaxf(acc[ms][ns][half * 2 + 0], 0.f);
                        float v1 = fmaxf(acc[ms][ns][half * 2 + 1], 0.f);
                        v0 *= v0; v1 *= v1;
                        *(uint32_t*)(oh + cc) = hpack2(v0, v1);
                    }
                } else {
                    int   pr = g_tl[idx];
                    float gt = g_gl[idx];
                    float* yo = g_ys + (size_t)pr * DDIM + nb;
#pragma unroll
                    for (int ns = 0; ns < 8; ns++) {
                        int cc = wn + ns * 8 + (lane & 3) * 2;
                        *(float2*)(yo + cc) =
                            make_float2(acc[ms][ns][half * 2 + 0] * gt,
                                        acc[ms][ns][half * 2 + 1] * gt);
                    }
                }
            }
        }
    }
}

__global__ void combine_kernel(float* __restrict__ out) {
    size_t i = (size_t)blockIdx.x * blockDim.x + threadIdx.x;  // float4 idx
    const float4* ys = (const float4*)g_ys;
    size_t t = i >> 8;
    size_t d = i & 255;
    float4 a = ys[(t * 2 + 0) * 256 + d];
    float4 b = ys[(t * 2 + 1) * 256 + d];
    ((float4*)out)[i] = make_float4(a.x + b.x, a.y + b.y, a.z + b.z, a.w + b.w);
}

// ---------------- launcher ----------------
extern "C" void kernel_launch(void* const* d_in, const int* in_sizes, int n_in,
                              void* d_out, int out_size) {
    const float* x  = (const float*)d_in[0];
    const float* nz = (const float*)d_in[1];
    const float* Wr = (const float*)d_in[2];
    const float* Wn = (const float*)d_in[3];
    const float* W1 = (const float*)d_in[4];
    const float* W2 = (const float*)d_in[5];
    float* out = (float*)d_out;

    cudaFuncSetAttribute(moe_mma<0>, cudaFuncAttributeMaxDynamicSharedMemorySize, DSMEM);
    cudaFuncSetAttribute(moe_mma<1>, cudaFuncAttributeMaxDynamicSharedMemorySize, DSMEM);

    zero_meta_kernel<<<1, 32>>>();                                   // 1
    prep_kernel<<<PB_RT, 256>>>(x, nz, Wr, Wn, W1, W2);              // 2
    scanbuild_kernel<<<1, 1024>>>();                                 // 3
    // 4 (profiled): GEMM1  M=cnt N=4096 K=1024, 1 term
    moe_mma<0><<<dim3(NTOK / 128, HDIM / 256, NEXP), 256, DSMEM>>>();
    // 5: GEMM2  M=cnt N=1024 K=4096, 1 term
    moe_mma<1><<<dim3(DDIM / 256, NTOK / 128, NEXP), 256, DSMEM>>>();
    combine_kernel<<<(NTOK * DDIM / 4) / 256, 256>>>(out);           // 6
}

// round 10
// speedup vs baseline: 2.8676x; 1.0018x over previous
#include <cuda_runtime.h>
#include <cuda_fp16.h>
#include <math.h>
#include <stdint.h>

#define NTOK 8192
#define DDIM 1024
#define HDIM 4096
#define NEXP 8
#define NPAIR (NTOK * 2)

// ---------------- scratch (device globals: allocation-free rule) ----------------
__device__ __half gXh[(size_t)NTOK * DDIM];   // fp16 x (token order)
__device__ __half gH[(size_t)NPAIR * HDIM];   // h = relu(u)^2, fp16, grouped
__device__ __half gW1h[(size_t)NEXP * DDIM * HDIM];
__device__ __half gW2h[(size_t)NEXP * HDIM * DDIM];
__device__ float g_ys[(size_t)NPAIR * DDIM];
__device__ int   g_tl[NPAIR];
__device__ float g_gl[NPAIR];
__device__ int   g_counts[NEXP];
__device__ int   g_offsets[NEXP + 1];
__device__ int   g_cursor[NEXP];
__device__ int   g_tok_e[NTOK];
__device__ float g_tok_g[NTOK * 2];

// ---------------- helpers ----------------
__device__ __forceinline__ uint32_t hpack2(float a, float b) {
    __half2 h = __floats2half2_rn(a, b);
    return *(uint32_t*)&h;
}

// ---------------- launch 1: zero meta ----------------
__global__ void zero_meta_kernel() {
    int i = threadIdx.x;
    if (i < NEXP) { g_counts[i] = 0; g_cursor[i] = 0; }
}

// ---------------- launch 2: fused prep (W1 hi | W2 hi | X hi | route) ----
#define PB_W1 32768
#define PB_W2 65536
#define PB_X  73728
#define PB_RT 74752

__global__ __launch_bounds__(256)
void prep_kernel(const float* __restrict__ x, const float* __restrict__ noisep,
                 const float* __restrict__ Wr, const float* __restrict__ Wn,
                 const float* __restrict__ W1, const float* __restrict__ W2) {
    int b = blockIdx.x, tid = threadIdx.x;
    if (b < PB_W2) {
        const float* W = (b < PB_W1) ? W1 : W2;
        __half* oh = (b < PB_W1) ? gW1h : gW2h;
        size_t i = ((size_t)(b < PB_W1 ? b : b - PB_W1) * 256 + tid);
        float4 v = ((const float4*)W)[i];
        *(uint2*)(oh + i * 4) = make_uint2(hpack2(v.x, v.y), hpack2(v.z, v.w));
    } else if (b < PB_X) {
        int t = b - PB_W2;
        float4 v = ((const float4*)(x + (size_t)t * DDIM))[tid];
        size_t o = (size_t)t * DDIM + tid * 4;
        *(uint2*)(gXh + o) = make_uint2(hpack2(v.x, v.y), hpack2(v.z, v.w));
    } else {
        // router: one warp per token
        int warp = tid >> 5, lane = tid & 31;
        int t = (b - PB_X) * 8 + warp;
        const float* xr = x + (size_t)t * DDIM;
        float xs[32];
#pragma unroll
        for (int i = 0; i < 32; i++) xs[i] = xr[lane + 32 * i];
        float nz[NEXP];
#pragma unroll
        for (int e = 0; e < NEXP; e++) {
            const float* wr = Wr + e * DDIM;
            const float* wn = Wn + e * DDIM;
            float a = 0.f, bb = 0.f;
#pragma unroll
            for (int i = 0; i < 32; i++) {
                float xv = xs[i];
                a  = fmaf(xv, wr[lane + 32 * i], a);
                bb = fmaf(xv, wn[lane + 32 * i], bb);
            }
#pragma unroll
            for (int o = 16; o > 0; o >>= 1) {
                a  += __shfl_xor_sync(0xffffffffu, a, o);
                bb += __shfl_xor_sync(0xffffffffu, bb, o);
            }
            float sp = fmaxf(bb, 0.f) + log1pf(expf(-fabsf(bb)));
            nz[e] = a + noisep[t * NEXP + e] * sp;
        }
        if (lane == 0) {
            int e0 = 0; float v0 = nz[0];
#pragma unroll
            for (int e = 1; e < NEXP; e++) if (nz[e] > v0) { v0 = nz[e]; e0 = e; }
            int e1 = (e0 == 0) ? 1 : 0; float v1 = nz[e1];
#pragma unroll
            for (int e = 0; e < NEXP; e++)
                if (e != e0 && nz[e] > v1) { v1 = nz[e]; e1 = e; }
            float m  = fmaxf(v0, v1);
            float z0 = expf(v0 - m), z1 = expf(v1 - m);
            float inv = 1.f / (z0 + z1);
            g_tok_e[t] = e0 | (e1 << 8);
            g_tok_g[t * 2 + 0] = z0 * inv;
            g_tok_g[t * 2 + 1] = z1 * inv;
            atomicAdd(&g_counts[e0], 1);
            atomicAdd(&g_counts[e1], 1);
        }
    }
}

// ---------------- launch 3: scan + build (single CTA) ----------------
__global__ void scanbuild_kernel() {
    int tid = threadIdx.x;
    if (tid == 0) {
        int s = 0;
        for (int e = 0; e < NEXP; e++) { g_offsets[e] = s; s += g_counts[e]; }
        g_offsets[NEXP] = s;
    }
    __syncthreads();
    for (int t = tid; t < NTOK; t += 1024) {
        int ee = g_tok_e[t];
        int e0 = ee & 0xff, e1 = ee >> 8;
        int s  = atomicAdd(&g_cursor[e0], 1);
        int i0 = g_offsets[e0] + s;
        g_tl[i0] = t * 2;     g_gl[i0] = g_tok_g[t * 2];
        s = atomicAdd(&g_cursor[e1], 1);
        int i1 = g_offsets[e1] + s;
        g_tl[i1] = t * 2 + 1; g_gl[i1] = g_tok_g[t * 2 + 1];
    }
}

// ---------------- mma helpers ----------------
__device__ __forceinline__ void ldsm4(uint32_t (&r)[4], uint32_t a) {
    asm volatile("ldmatrix.sync.aligned.m8n8.x4.shared.b16 {%0,%1,%2,%3}, [%4];\n"
                 : "=r"(r[0]), "=r"(r[1]), "=r"(r[2]), "=r"(r[3]) : "r"(a));
}
__device__ __forceinline__ void ldsm4t(uint32_t (&r)[4], uint32_t a) {
    asm volatile("ldmatrix.sync.aligned.m8n8.x4.trans.shared.b16 {%0,%1,%2,%3}, [%4];\n"
                 : "=r"(r[0]), "=r"(r[1]), "=r"(r[2]), "=r"(r[3]) : "r"(a));
}
__device__ __forceinline__ void mma16816(float (&c)[4], const uint32_t (&a)[4],
                                         uint32_t b0, uint32_t b1) {
    asm volatile(
        "mma.sync.aligned.m16n8k16.row.col.f32.f16.f16.f32 "
        "{%0,%1,%2,%3},{%4,%5,%6,%7},{%8,%9},{%0,%1,%2,%3};\n"
        : "+f"(c[0]), "+f"(c[1]), "+f"(c[2]), "+f"(c[3])
        : "r"(a[0]), "r"(a[1]), "r"(a[2]), "r"(a[3]), "r"(b0), "r"(b1));
}
__device__ __forceinline__ void cpa16(uint32_t d, const void* s) {
    asm volatile("cp.async.cg.shared.global [%0], [%1], 16;" :: "r"(d), "l"(s)
                 : "memory");
}
__device__ __forceinline__ void cpa_commit() {
    asm volatile("cp.async.commit_group;" ::: "memory");
}
__device__ __forceinline__ void cpa_wait2() {
    asm volatile("cp.async.wait_group 2;" ::: "memory");
}

// smem geometry: CTA tile 128(M) x 256(N), BK=64.
// A: 128 rows x 144B pitch (128B data + 16 pad)  -> rows at banks 0,4,..,28: conflict-free
// B: 64 k-rows x 528B pitch (512B data + 16 pad) -> rows at banks 0,4,..,28: conflict-free
//    (was 544B: offset 8 banks/row -> 2-way conflict on every ldmatrix.trans phase)
#define A_BYTES 18432
#define B_PITCH 528
#define B_BYTES (64 * B_PITCH)
#define STG     (A_BYTES + B_BYTES)
#define NSTAGE  4
#define DSMEM   (NSTAGE * STG)

// ---------------- grouped fp16 mma.sync GEMM (1 term both modes) ----------------
// MODE 0: h = relu(x @ W1h)^2 -> gH (fp16)   K=1024 N=4096
// MODE 1: ys = gate * (h @ W2h) -> g_ys      K=4096 N=1024
template <int MODE>
__global__ __launch_bounds__(256, 1)
void moe_mma() {
    constexpr int K   = (MODE == 0) ? DDIM : HDIM;
    constexpr int NGL = (MODE == 0) ? HDIM : DDIM;
    constexpr int NC  = K / 64;

    const int e   = blockIdx.z;
    const int cnt = g_counts[e];
    const int mT  = (MODE == 0) ? blockIdx.x : blockIdx.y;
    if (mT * 128 >= cnt) return;
    const int nT  = (MODE == 0) ? blockIdx.y : blockIdx.x;
    const int off = g_offsets[e];
    const int nb  = nT * 256;

    extern __shared__ char dsm[];
    const uint32_t ab = (uint32_t)__cvta_generic_to_shared(dsm);

    const int tid = threadIdx.x;
    const int warp = tid >> 5, lane = tid & 31;

    const __half* Ah = (MODE == 0) ? gXh : gH;
    const __half* Bh = ((MODE == 0) ? gW1h : gW2h) + (size_t)e * DDIM * HDIM;

    // ---- cp.async slots: A 4 rows x 16B/thread, B 8 rows x 16B/thread ----
    const int aC = tid & 7;            // 16B chunk in 128B row
    const int aR = tid >> 3;           // 0..31
    uint32_t aSrc[4]; uint32_t aDst[4];
#pragma unroll
    for (int i = 0; i < 4; i++) {
        int r  = aR + i * 32;
        int rm = min(mT * 128 + r, cnt - 1);
        uint32_t rowbase;
        if (MODE == 0) rowbase = (uint32_t)(g_tl[off + rm] >> 1) * DDIM;
        else           rowbase = (uint32_t)(off + rm) * HDIM;
        aSrc[i] = rowbase + aC * 8;
        aDst[i] = (uint32_t)(r * 144 + aC * 16);
    }
    const int bC = tid & 31;           // 16B chunk in 512B row
    const int bR = tid >> 5;           // 0..7
    uint32_t bSrc[8]; uint32_t bDst[8];
#pragma unroll
    for (int i = 0; i < 8; i++) {
        int r = bR + i * 8;
        bSrc[i] = (uint32_t)(r * NGL + nb + bC * 8);
        bDst[i] = (uint32_t)(r * B_PITCH + bC * 16);
    }

    auto ldc = [&](int c) {
        uint32_t sb = ab + (uint32_t)(c % NSTAGE) * STG;
        uint32_t k0 = c * 64;
#pragma unroll
        for (int i = 0; i < 4; i++)
            cpa16(sb + aDst[i], Ah + aSrc[i] + k0);
        uint32_t bk = k0 * NGL;
#pragma unroll
        for (int i = 0; i < 8; i++)
            cpa16(sb + A_BYTES + bDst[i], Bh + bSrc[i] + bk);
        cpa_commit();
    };

    // warp grid: 2 (M) x 4 (N) -> 64x64 warp tile
    const int wm = (warp >> 2) * 64;
    const int wn = (warp & 3) * 64;

    float acc[4][8][4];
#pragma unroll
    for (int a = 0; a < 4; a++)
#pragma unroll
        for (int b = 0; b < 8; b++)
#pragma unroll
            for (int c = 0; c < 4; c++) acc[a][b][c] = 0.f;

    const int aRow  = lane & 15;
    const int aCol  = (lane >> 4) << 3;
    const int bRowL = ((lane >> 3) & 1) * 8 + (lane & 7);
    const int bColL = (lane >> 4) * 8;

    auto compute = [&](int c) {
        uint32_t sb = ab + (uint32_t)(c % NSTAGE) * STG;
#pragma unroll
        for (int ks = 0; ks < 4; ks++) {
            uint32_t afh[4][4];
#pragma unroll
            for (int ms = 0; ms < 4; ms++)
                ldsm4(afh[ms], sb + (uint32_t)((wm + ms * 16 + aRow) * 144 +
                                               (ks * 16 + aCol) * 2));
#pragma unroll
            for (int g = 0; g < 4; g++) {
                uint32_t brow = (uint32_t)((ks * 16 + bRowL) * B_PITCH +
                                           (wn + g * 16 + bColL) * 2);
                uint32_t qh[4];
                ldsm4t(qh, sb + A_BYTES + brow);
                // 8 independent accumulators back-to-back
#pragma unroll
                for (int ms = 0; ms < 4; ms++) {
                    mma16816(acc[ms][g * 2 + 0], afh[ms], qh[0], qh[1]);
                    mma16816(acc[ms][g * 2 + 1], afh[ms], qh[2], qh[3]);
                }
            }
        }
    };

    // 4-stage pipeline, 1 barrier per chunk, prefetch 3 ahead
    ldc(0);
    ldc(1);
    ldc(2);
    for (int c = 0; c < NC; c++) {
        cpa_wait2();
        __syncthreads();
        if (c + 3 < NC) ldc(c + 3); else cpa_commit();
        compute(c);
    }

    // ---------------- epilogue ----------------
#pragma unroll
    for (int ms = 0; ms < 4; ms++) {
        int r0 = wm + ms * 16 + (lane >> 2);
#pragma unroll
        for (int half = 0; half < 2; half++) {
            int r  = r0 + half * 8;
            int gm = mT * 128 + r;
            if (gm < cnt) {
                int idx = off + gm;
                if (MODE == 0) {
                    __half* oh = gH + (size_t)idx * HDIM + nb;
#pragma unroll
                    for (int ns = 0; ns < 8; ns++) {
                        int cc  = wn + ns * 8 + (lane & 3) * 2;
                        float v0 = fmaxf(acc[ms][ns][half * 2 + 0], 0.f);
                        float v1 = fmaxf(acc[ms][ns][half * 2 + 1], 0.f);
                        v0 *= v0; v1 *= v1;
                        *(uint32_t*)(oh + cc) = hpack2(v0, v1);
                    }
                } else {
                    int   pr = g_tl[idx];
                    float gt = g_gl[idx];
                    float* yo = g_ys + (size_t)pr * DDIM + nb;
#pragma unroll
                    for (int ns = 0; ns < 8; ns++) {
                        int cc = wn + ns * 8 + (lane & 3) * 2;
                        *(float2*)(yo + cc) =
                            make_float2(acc[ms][ns][half * 2 + 0] * gt,
                                        acc[ms][ns][half * 2 + 1] * gt);
                    }
                }
            }
        }
    }
}

__global__ void combine_kernel(float* __restrict__ out) {
    size_t i = (size_t)blockIdx.x * blockDim.x + threadIdx.x;  // float4 idx
    const float4* ys = (const float4*)g_ys;
    size_t t = i >> 8;
    size_t d = i & 255;
    float4 a = ys[(t * 2 + 0) * 256 + d];
    float4 b = ys[(t * 2 + 1) * 256 + d];
    ((float4*)out)[i] = make_float4(a.x + b.x, a.y + b.y, a.z + b.z, a.w + b.w);
}

// ---------------- launcher ----------------
extern "C" void kernel_launch(void* const* d_in, const int* in_sizes, int n_in,
                              void* d_out, int out_size) {
    const float* x  = (const float*)d_in[0];
    const float* nz = (const float*)d_in[1];
    const float* Wr = (const float*)d_in[2];
    const float* Wn = (const float*)d_in[3];
    const float* W1 = (const float*)d_in[4];
    const float* W2 = (const float*)d_in[5];
    float* out = (float*)d_out;

    cudaFuncSetAttribute(moe_mma<0>, cudaFuncAttributeMaxDynamicSharedMemorySize, DSMEM);
    cudaFuncSetAttribute(moe_mma<1>, cudaFuncAttributeMaxDynamicSharedMemorySize, DSMEM);

    zero_meta_kernel<<<1, 32>>>();                                   // 1
    prep_kernel<<<PB_RT, 256>>>(x, nz, Wr, Wn, W1, W2);              // 2
    scanbuild_kernel<<<1, 1024>>>();                                 // 3
    // 4 (profiled): GEMM1  M=cnt N=4096 K=1024, 1 term
    moe_mma<0><<<dim3(NTOK / 128, HDIM / 256, NEXP), 256, DSMEM>>>();
    // 5: GEMM2  M=cnt N=1024 K=4096, 1 term
    moe_mma<1><<<dim3(DDIM / 256, NTOK / 128, NEXP), 256, DSMEM>>>();
    combine_kernel<<<(NTOK * DDIM / 4) / 256, 256>>>(out);           // 6
}